// round 3
// baseline (speedup 1.0000x reference)
#include <cuda_runtime.h>
#include <math.h>

#define NB   32          // batch
#define NC   512         // channels
#define NHW  1024        // H*W
#define NGRP 32
#define CPG  16          // channels per group

// ---------------- scratch (static device arrays; no allocation) ----------------
__device__ float g_hin[(size_t)NB * NC * NHW];        // 64 MB groupnorm output
__device__ float g_qkv[(size_t)NB * 3 * NC * NHW];    // 192 MB
__device__ float g_S  [(size_t)NB * NHW * NHW];       // 128 MB attention scores
__device__ float g_H  [(size_t)NB * NC * NHW];        // 64 MB attn output

// ---------------- GroupNorm ----------------
__global__ __launch_bounds__(256) void groupnorm_kernel(
    const float* __restrict__ x, const float* __restrict__ gamma,
    const float* __restrict__ beta, float* __restrict__ y)
{
    __shared__ float sred[16];
    int b = blockIdx.x >> 5;
    int g = blockIdx.x & 31;
    const float4* xp = reinterpret_cast<const float4*>(x + ((size_t)b * NC + g * CPG) * NHW);
    float4*       yp = reinterpret_cast<float4*>      (y + ((size_t)b * NC + g * CPG) * NHW);
    const int N4 = CPG * NHW / 4;   // 4096 float4s

    float s = 0.f, s2 = 0.f;
    for (int i = threadIdx.x; i < N4; i += 256) {
        float4 v = xp[i];
        s  += v.x + v.y + v.z + v.w;
        s2 += v.x*v.x + v.y*v.y + v.z*v.z + v.w*v.w;
    }
    #pragma unroll
    for (int o = 16; o > 0; o >>= 1) {
        s  += __shfl_xor_sync(0xffffffffu, s,  o);
        s2 += __shfl_xor_sync(0xffffffffu, s2, o);
    }
    int warp = threadIdx.x >> 5, lane = threadIdx.x & 31;
    if (lane == 0) { sred[warp] = s; sred[8 + warp] = s2; }
    __syncthreads();
    if (threadIdx.x == 0) {
        float ts = 0.f, ts2 = 0.f;
        #pragma unroll
        for (int w = 0; w < 8; w++) { ts += sred[w]; ts2 += sred[8 + w]; }
        const float invn = 1.0f / (CPG * NHW);
        float mean = ts * invn;
        float var  = ts2 * invn - mean * mean;
        sred[0] = mean;
        sred[1] = rsqrtf(var + 1e-5f);
    }
    __syncthreads();
    float mean = sred[0], inv = sred[1];
    for (int i = threadIdx.x; i < N4; i += 256) {
        int c = g * CPG + (i >> 8);             // 256 float4 per channel
        float gm = gamma[c] * inv;
        float bt = beta[c] - mean * gm;
        float4 v = xp[i];
        v.x = v.x * gm + bt; v.y = v.y * gm + bt;
        v.z = v.z * gm + bt; v.w = v.w * gm + bt;
        yp[i] = v;
    }
}

// ---------------- Softmax over 32-element segments (reference: softmax over
// last axis J of [B,H,W,I,J] — i.e. each contiguous 32-float run of S) -------
// One float4 per thread; 8 consecutive threads cover one 32-float segment.
__global__ __launch_bounds__(256) void softmax32_kernel(float4* __restrict__ S)
{
    long long i = (long long)blockIdx.x * 256 + threadIdx.x;
    float4 v = S[i];
    float m = fmaxf(fmaxf(v.x, v.y), fmaxf(v.z, v.w));
    #pragma unroll
    for (int o = 1; o < 8; o <<= 1) m = fmaxf(m, __shfl_xor_sync(0xffffffffu, m, o));
    v.x = __expf(v.x - m); v.y = __expf(v.y - m);
    v.z = __expf(v.z - m); v.w = __expf(v.w - m);
    float s = v.x + v.y + v.z + v.w;
    #pragma unroll
    for (int o = 1; o < 8; o <<= 1) s += __shfl_xor_sync(0xffffffffu, s, o);
    float inv = 1.0f / s;
    v.x *= inv; v.y *= inv; v.z *= inv; v.w *= inv;
    S[i] = v;
}

// ---------------- Generic batched SGEMM: C[m,n] = alpha*sum_k A[m,k]*B[n,k] (+bias[m]) (+res) ----------------
// AKC: A's k-stride == 1 (m-stride = sAm). !AKC: A's m-stride == 1 (k-stride = sAk).
// BKC: B's k-stride == 1 (n-stride = sBn). !BKC: B's n-stride == 1 (k-stride = sBk).
// C is [m][n] with n contiguous, m-stride sCm. M,N multiples of 128; K multiple of 8.
template<bool AKC, bool BKC>
__global__ __launch_bounds__(256) void sgemm_kernel(
    const float* __restrict__ A, const float* __restrict__ B, float* __restrict__ C,
    int M, int N, int K,
    int sA, long long batchA,     // sA = sAm if AKC else sAk
    int sB, long long batchB,     // sB = sBn if BKC else sBk
    int sCm, long long batchC,
    float alpha,
    const float* __restrict__ bias,
    const float* __restrict__ res, long long batchRes)
{
    __shared__ float As[8][132];
    __shared__ float Bs[8][132];

    const int b = blockIdx.z;
    A += (long long)b * batchA;
    B += (long long)b * batchB;
    C += (long long)b * batchC;
    if (res) res += (long long)b * batchRes;

    const int m0 = blockIdx.y * 128;
    const int n0 = blockIdx.x * 128;
    const int tid = threadIdx.x;
    const int tx = tid & 15, ty = tid >> 4;

    float acc[8][8];
    #pragma unroll
    for (int i = 0; i < 8; i++)
        #pragma unroll
        for (int j = 0; j < 8; j++) acc[i][j] = 0.f;

    for (int k0 = 0; k0 < K; k0 += 8) {
        // ---- load A tile ----
        if (AKC) {
            int row = tid >> 1;
            int kk  = (tid & 1) * 4;
            float4 v = *reinterpret_cast<const float4*>(A + (long long)(m0 + row) * sA + (k0 + kk));
            As[kk + 0][row] = v.x; As[kk + 1][row] = v.y;
            As[kk + 2][row] = v.z; As[kk + 3][row] = v.w;
        } else {
            int kk = tid >> 5;
            int mm = (tid & 31) * 4;
            float4 v = *reinterpret_cast<const float4*>(A + (long long)(k0 + kk) * sA + (m0 + mm));
            *reinterpret_cast<float4*>(&As[kk][mm]) = v;
        }
        // ---- load B tile ----
        if (BKC) {
            int row = tid >> 1;
            int kk  = (tid & 1) * 4;
            float4 v = *reinterpret_cast<const float4*>(B + (long long)(n0 + row) * sB + (k0 + kk));
            Bs[kk + 0][row] = v.x; Bs[kk + 1][row] = v.y;
            Bs[kk + 2][row] = v.z; Bs[kk + 3][row] = v.w;
        } else {
            int kk = tid >> 5;
            int nn = (tid & 31) * 4;
            float4 v = *reinterpret_cast<const float4*>(B + (long long)(k0 + kk) * sB + (n0 + nn));
            *reinterpret_cast<float4*>(&Bs[kk][nn]) = v;
        }
        __syncthreads();

        #pragma unroll
        for (int k = 0; k < 8; k++) {
            float a[8], bb[8];
            #pragma unroll
            for (int i = 0; i < 8; i++) a[i]  = As[k][ty * 8 + i];
            #pragma unroll
            for (int j = 0; j < 8; j++) bb[j] = Bs[k][tx * 8 + j];
            #pragma unroll
            for (int i = 0; i < 8; i++)
                #pragma unroll
                for (int j = 0; j < 8; j++)
                    acc[i][j] = fmaf(a[i], bb[j], acc[i][j]);
        }
        __syncthreads();
    }

    // ---- epilogue ----
    #pragma unroll
    for (int i = 0; i < 8; i++) {
        int m = m0 + ty * 8 + i;
        float bi = bias ? bias[m] : 0.0f;
        long long cb = (long long)m * sCm + n0 + tx * 8;
        #pragma unroll
        for (int j0 = 0; j0 < 8; j0 += 4) {
            float4 v;
            v.x = alpha * acc[i][j0 + 0] + bi;
            v.y = alpha * acc[i][j0 + 1] + bi;
            v.z = alpha * acc[i][j0 + 2] + bi;
            v.w = alpha * acc[i][j0 + 3] + bi;
            if (res) {
                float4 rv = *reinterpret_cast<const float4*>(res + cb + j0);
                v.x += rv.x; v.y += rv.y; v.z += rv.z; v.w += rv.w;
            }
            *reinterpret_cast<float4*>(C + cb + j0) = v;
        }
    }
}

// ---------------- launch ----------------
extern "C" void kernel_launch(void* const* d_in, const int* in_sizes, int n_in,
                              void* d_out, int out_size)
{
    const float* x       = (const float*)d_in[0];
    const float* gamma   = (const float*)d_in[1];
    const float* beta    = (const float*)d_in[2];
    const float* qkv_w   = (const float*)d_in[3];
    const float* qkv_b   = (const float*)d_in[4];
    const float* proj_w  = (const float*)d_in[5];
    const float* proj_b  = (const float*)d_in[6];
    float* out = (float*)d_out;

    float *hin, *qkv, *Sb, *Hb;
    cudaGetSymbolAddress((void**)&hin, g_hin);
    cudaGetSymbolAddress((void**)&qkv, g_qkv);
    cudaGetSymbolAddress((void**)&Sb,  g_S);
    cudaGetSymbolAddress((void**)&Hb,  g_H);

    const long long sCHW  = (long long)NC * NHW;       // 512*1024
    const long long s3CHW = 3LL * NC * NHW;            // qkv batch stride
    const long long sSS   = (long long)NHW * NHW;      // S batch stride
    const float attn_scale = 1.0f / sqrtf((float)NC);  // s^2 = 1/sqrt(C)

    // 1) GroupNorm
    groupnorm_kernel<<<NB * NGRP, 256>>>(x, gamma, beta, hin);

    // 2) QKV: [1536x512] @ hin[512x1024] per batch, +bias
    sgemm_kernel<true, false><<<dim3(NHW / 128, 3 * NC / 128, NB), 256>>>(
        qkv_w, hin, qkv, 3 * NC, NHW, NC,
        NC, 0LL,            // A: row-major [O,C], k contiguous, m-stride=NC, shared across batch
        NHW, sCHW,          // B: hin [C][HW], n contiguous, k-stride=NHW
        NHW, s3CHW,
        1.0f, qkv_b, nullptr, 0LL);

    // 3) S = (Q^T K) * 1/sqrt(C) : [1024x1024], K=512
    sgemm_kernel<false, false><<<dim3(NHW / 128, NHW / 128, NB), 256>>>(
        qkv /*Q*/, qkv + (long long)NC * NHW /*K*/, Sb, NHW, NHW, NC,
        NHW, s3CHW,         // A: Q [C][HW], m contiguous, k-stride=NHW
        NHW, s3CHW,         // B: K [C][HW], n contiguous, k-stride=NHW
        NHW, sSS,
        attn_scale, nullptr, nullptr, 0LL);

    // 4) softmax over each 32-element (last axis J) segment of S
    softmax32_kernel<<<(int)((size_t)NB * NHW * NHW / 4 / 256), 256>>>(
        reinterpret_cast<float4*>(Sb));

    // 5) H = V @ P^T : [512x1024], K=1024 (sum over all i,j)
    sgemm_kernel<true, true><<<dim3(NHW / 128, NC / 128, NB), 256>>>(
        qkv + 2LL * NC * NHW /*V*/, Sb /*P*/, Hb, NC, NHW, NHW,
        NHW, s3CHW,         // A: V [C][HW], k contiguous, m-stride=NHW
        NHW, sSS,           // B: P [HW][HW], k contiguous, n-stride=NHW
        NHW, sCHW,
        1.0f, nullptr, nullptr, 0LL);

    // 6) out = x + proj_w @ H + proj_b
    sgemm_kernel<true, false><<<dim3(NHW / 128, NC / 128, NB), 256>>>(
        proj_w, Hb, out, NC, NHW, NC,
        NC, 0LL,            // A: proj_w row-major [C,C]
        NHW, sCHW,          // B: H [C][HW], n contiguous
        NHW, sCHW,
        1.0f, proj_b, x, sCHW);
}

// round 5
// speedup vs baseline: 2.0768x; 2.0768x over previous
#include <cuda_runtime.h>
#include <cuda_bf16.h>
#include <math.h>
#include <stdint.h>

#define NB   32
#define NC   512
#define NHW  1024
#define CHW  (NC * NHW)

// ---------------- scratch ----------------
__device__ float g_qkv[(size_t)NB * 3 * CHW];      // [b][1536][1024]  (Q | K | V)
__device__ float g_S  [(size_t)NB * NHW * NHW];    // [b][p][q] post-softmax
__device__ float g_H  [(size_t)NB * CHW];          // [b][c][p]
__device__ float g_stats[NB * 32 * 2];             // (mean, rstd) per (b,g)

// ---------------- PTX helpers (baseline ISA only: sm_80-era features) ----------------
__device__ __forceinline__ uint32_t smem_u32(const void* p) {
    uint32_t a;
    asm("{ .reg .u64 t; cvta.to.shared.u64 t, %1; cvt.u32.u64 %0, t; }" : "=r"(a) : "l"(p));
    return a;
}
#define LDSM4(R, a) \
    asm volatile("ldmatrix.sync.aligned.m8n8.x4.shared.b16 {%0,%1,%2,%3}, [%4];" \
        : "=r"((R)[0]), "=r"((R)[1]), "=r"((R)[2]), "=r"((R)[3]) : "r"(a))
#define LDSM4T(R, a) \
    asm volatile("ldmatrix.sync.aligned.m8n8.x4.trans.shared.b16 {%0,%1,%2,%3}, [%4];" \
        : "=r"((R)[0]), "=r"((R)[1]), "=r"((R)[2]), "=r"((R)[3]) : "r"(a))

__device__ __forceinline__ void mma16816(float* d, const uint32_t* a, uint32_t b0, uint32_t b1) {
    asm volatile("mma.sync.aligned.m16n8k16.row.col.f32.bf16.bf16.f32 "
                 "{%0,%1,%2,%3}, {%4,%5,%6,%7}, {%8,%9}, {%0,%1,%2,%3};"
                 : "+f"(d[0]), "+f"(d[1]), "+f"(d[2]), "+f"(d[3])
                 : "r"(a[0]), "r"(a[1]), "r"(a[2]), "r"(a[3]), "r"(b0), "r"(b1));
}

// fp32x4 -> bf16 hi x4 + bf16 lo x4
__device__ __forceinline__ void split4(float4 v, uint2& h, uint2& l) {
    __nv_bfloat162 h0 = __float22bfloat162_rn(make_float2(v.x, v.y));
    __nv_bfloat162 h1 = __float22bfloat162_rn(make_float2(v.z, v.w));
    float2 f0 = __bfloat1622float2(h0), f1 = __bfloat1622float2(h1);
    __nv_bfloat162 l0 = __float22bfloat162_rn(make_float2(v.x - f0.x, v.y - f0.y));
    __nv_bfloat162 l1 = __float22bfloat162_rn(make_float2(v.z - f1.x, v.w - f1.y));
    h.x = *(uint32_t*)&h0; h.y = *(uint32_t*)&h1;
    l.x = *(uint32_t*)&l0; l.y = *(uint32_t*)&l1;
}

// smem: 2 stages x (AH | AL | BH | BL), slot 10240B
//   direct tile: 128 rows x 80B (k-contig, stride pad for ldsm conflicts)
//   trans  tile:  32 krows x 272B (m-contig source, ldmatrix.trans)
#define SLOT   10240
#define STAGEB 40960
#define SMEMB  81920

// EPI: 0=QKV(+bias), 1=S(alpha + fused 32-wide softmax), 2=H plain, 3=proj(+bias+residual)
// TA/TB: operand loaded via transpose (source is [k][mn], m/n-contiguous)
// GNB: apply groupnorm affine to B while loading (B source = x)
template<int EPI, bool TA, bool TB, bool GNB>
__global__ __launch_bounds__(256)
void tc_gemm(const float* __restrict__ A, long long sAb, int lda,
             const float* __restrict__ B, long long sBb, int ldb,
             int Ktot, float* __restrict__ C, long long sCb,
             const float* __restrict__ bias, const float* __restrict__ res,
             const float* __restrict__ gamma, const float* __restrict__ beta,
             const float* __restrict__ stats, float alpha)
{
    extern __shared__ char sm[];
    const int tid = threadIdx.x, l = tid & 31, wid = tid >> 5;
    const int bz = blockIdx.z;
    const int m0 = blockIdx.y * 128, n0 = blockIdx.x * 128;
    const int wm = (wid >> 2) * 64, wn = (wid & 3) * 32;

    const float* Ag = A + (long long)bz * sAb + (TA ? (long long)m0 : (long long)m0 * lda);
    const float* Bg = B + (long long)bz * sBb + (TB ? (long long)n0 : (long long)n0 * ldb);

    // ldg addressing: thread t -> (tr = t>>3, tc = t&7)
    const int tr = tid >> 3, tc = tid & 7;
    const long long aBase = (long long)tr * lda + tc * 4;
    const long long bBase = (long long)tr * ldb + tc * 4;
    const long long aStepI = TA ? 32 : (long long)32 * lda;   // i = 0..3
    const long long bStepI = TB ? 32 : (long long)32 * ldb;
    const long long aStepS = TA ? (long long)32 * lda : 32;   // per k-stage
    const long long bStepS = TB ? (long long)32 * ldb : 32;
    const uint32_t aSts  = TA ? (uint32_t)(tr * 272 + tc * 8) : (uint32_t)(tr * 80 + tc * 8);
    const uint32_t bSts  = TB ? (uint32_t)(tr * 272 + tc * 8) : (uint32_t)(tr * 80 + tc * 8);
    const uint32_t aStsI = TA ? 64u : 2560u;
    const uint32_t bStsI = TB ? 64u : 2560u;

    // ldmatrix fragment addressing
    const uint32_t smb  = smem_u32(sm);
    const uint32_t dOff = (uint32_t)((l & 15) * 80 + (l >> 4) * 16);
    const uint32_t tOff = (uint32_t)(((l & 7) + ((l >> 4) << 3)) * 272 + ((l >> 3) & 1) * 16);
    const uint32_t aFragBase = TA ? (uint32_t)(wm * 2 + tOff) : (uint32_t)(wm * 80 + dOff);
    const uint32_t bFragBase = TB ? (uint32_t)(wn * 2 + tOff) : (uint32_t)(wn * 80 + dOff);
    const uint32_t aMT = TA ? 32u : 1280u;   // step per 16 rows/cols of m
    const uint32_t bG  = TB ? 32u : 1280u;   // step per 16 n
    const uint32_t aH  = TA ? 4352u : 32u;   // step per k16 half
    const uint32_t bH  = TB ? 4352u : 32u;

    float acc[4][4][4];
    #pragma unroll
    for (int i = 0; i < 4; i++)
        #pragma unroll
        for (int j = 0; j < 4; j++)
            #pragma unroll
            for (int k = 0; k < 4; k++) acc[i][j][k] = 0.f;

    float4 va[4], vb[4];
    float gnm = 1.f, gnb = 0.f;

    auto LDGA = [&](int s) {
        long long k0 = (long long)s * aStepS;
        #pragma unroll
        for (int i = 0; i < 4; i++) va[i] = *(const float4*)(Ag + aBase + i * aStepI + k0);
    };
    auto LDGB = [&](int s) {
        long long k0 = (long long)s * bStepS;
        #pragma unroll
        for (int i = 0; i < 4; i++) vb[i] = *(const float4*)(Bg + bBase + i * bStepI + k0);
        if (GNB) {
            int c = s * 32 + tr;                      // channel = k row
            float mean = stats[(bz * 32 + (c >> 4)) * 2 + 0];
            float rstd = stats[(bz * 32 + (c >> 4)) * 2 + 1];
            gnm = gamma[c] * rstd;
            gnb = beta[c] - mean * gnm;
        }
    };
    auto STSA = [&](int buf) {
        char* ph = sm + buf * STAGEB;
        char* pl = ph + SLOT;
        #pragma unroll
        for (int i = 0; i < 4; i++) {
            uint2 h, lo; split4(va[i], h, lo);
            *(uint2*)(ph + aSts + i * aStsI) = h;
            *(uint2*)(pl + aSts + i * aStsI) = lo;
        }
    };
    auto STSB = [&](int buf) {
        char* ph = sm + buf * STAGEB + 2 * SLOT;
        char* pl = ph + SLOT;
        #pragma unroll
        for (int i = 0; i < 4; i++) {
            float4 v = vb[i];
            if (GNB) { v.x = v.x * gnm + gnb; v.y = v.y * gnm + gnb;
                       v.z = v.z * gnm + gnb; v.w = v.w * gnm + gnb; }
            uint2 h, lo; split4(v, h, lo);
            *(uint2*)(ph + bSts + i * bStsI) = h;
            *(uint2*)(pl + bSts + i * bStsI) = lo;
        }
    };
    auto COMPUTE = [&](int buf) {
        uint32_t base = smb + buf * STAGEB;
        #pragma unroll
        for (int h = 0; h < 2; h++) {
            uint32_t Ah[4][4], Al[4][4], Bh[2][4], Bl[2][4];
            #pragma unroll
            for (int mt = 0; mt < 4; mt++) {
                uint32_t ad = base + aFragBase + mt * aMT + h * aH;
                if (TA) { LDSM4T(Ah[mt], ad); LDSM4T(Al[mt], ad + SLOT); }
                else    { LDSM4 (Ah[mt], ad); LDSM4 (Al[mt], ad + SLOT); }
            }
            #pragma unroll
            for (int g = 0; g < 2; g++) {
                uint32_t bd = base + 2 * SLOT + bFragBase + g * bG + h * bH;
                if (TB) { LDSM4T(Bh[g], bd); LDSM4T(Bl[g], bd + SLOT); }
                else    { LDSM4 (Bh[g], bd); LDSM4 (Bl[g], bd + SLOT); }
            }
            #pragma unroll
            for (int mt = 0; mt < 4; mt++)
                #pragma unroll
                for (int nt = 0; nt < 4; nt++) {
                    float* d = acc[mt][nt];
                    uint32_t b0h = Bh[nt >> 1][nt & 1], b1h = Bh[nt >> 1][2 + (nt & 1)];
                    uint32_t b0l = Bl[nt >> 1][nt & 1], b1l = Bl[nt >> 1][2 + (nt & 1)];
                    mma16816(d, Ah[mt], b0h, b1h);
                    mma16816(d, Ah[mt], b0l, b1l);
                    mma16816(d, Al[mt], b0h, b1h);
                }
        }
    };

    // ---- pipeline ----
    const int NS = Ktot / 32;
    LDGA(0); LDGB(0);
    STSA(0); STSB(0);
    __syncthreads();
    for (int s = 0; s < NS; s++) {
        int cur = s & 1;
        if (s + 1 < NS) { LDGA(s + 1); LDGB(s + 1); }
        COMPUTE(cur);
        if (s + 1 < NS) { STSA(cur ^ 1); STSB(cur ^ 1); }
        __syncthreads();
    }

    // ---- epilogue ----
    float* Cb = C + (long long)bz * sCb;
    const float* Rb = (EPI == 3) ? (res + (long long)bz * sCb) : nullptr;

    if (EPI == 1) {
        #pragma unroll
        for (int mt = 0; mt < 4; mt++) {
            int r0 = m0 + wm + mt * 16 + (l >> 2);
            int r1 = r0 + 8;
            float vl[8], vh[8];
            #pragma unroll
            for (int nt = 0; nt < 4; nt++) {
                vl[2 * nt]     = acc[mt][nt][0] * alpha;
                vl[2 * nt + 1] = acc[mt][nt][1] * alpha;
                vh[2 * nt]     = acc[mt][nt][2] * alpha;
                vh[2 * nt + 1] = acc[mt][nt][3] * alpha;
            }
            float m_lo = vl[0], m_hi = vh[0];
            #pragma unroll
            for (int j = 1; j < 8; j++) { m_lo = fmaxf(m_lo, vl[j]); m_hi = fmaxf(m_hi, vh[j]); }
            m_lo = fmaxf(m_lo, __shfl_xor_sync(0xffffffffu, m_lo, 1));
            m_lo = fmaxf(m_lo, __shfl_xor_sync(0xffffffffu, m_lo, 2));
            m_hi = fmaxf(m_hi, __shfl_xor_sync(0xffffffffu, m_hi, 1));
            m_hi = fmaxf(m_hi, __shfl_xor_sync(0xffffffffu, m_hi, 2));
            float s_lo = 0.f, s_hi = 0.f;
            #pragma unroll
            for (int j = 0; j < 8; j++) {
                vl[j] = __expf(vl[j] - m_lo); s_lo += vl[j];
                vh[j] = __expf(vh[j] - m_hi); s_hi += vh[j];
            }
            s_lo += __shfl_xor_sync(0xffffffffu, s_lo, 1);
            s_lo += __shfl_xor_sync(0xffffffffu, s_lo, 2);
            s_hi += __shfl_xor_sync(0xffffffffu, s_hi, 1);
            s_hi += __shfl_xor_sync(0xffffffffu, s_hi, 2);
            float i_lo = 1.0f / s_lo, i_hi = 1.0f / s_hi;
            #pragma unroll
            for (int nt = 0; nt < 4; nt++) {
                int n = n0 + wn + nt * 8 + (l & 3) * 2;
                *(float2*)(Cb + (long long)r0 * NHW + n) =
                    make_float2(vl[2 * nt] * i_lo, vl[2 * nt + 1] * i_lo);
                *(float2*)(Cb + (long long)r1 * NHW + n) =
                    make_float2(vh[2 * nt] * i_hi, vh[2 * nt + 1] * i_hi);
            }
        }
    } else {
        #pragma unroll
        for (int mt = 0; mt < 4; mt++) {
            int r0 = m0 + wm + mt * 16 + (l >> 2);
            int r1 = r0 + 8;
            float b0v = 0.f, b1v = 0.f;
            if (EPI == 0 || EPI == 3) { b0v = bias[r0]; b1v = bias[r1]; }
            #pragma unroll
            for (int nt = 0; nt < 4; nt++) {
                int n = n0 + wn + nt * 8 + (l & 3) * 2;
                float2 v0 = make_float2(acc[mt][nt][0] + b0v, acc[mt][nt][1] + b0v);
                float2 v1 = make_float2(acc[mt][nt][2] + b1v, acc[mt][nt][3] + b1v);
                if (EPI == 3) {
                    float2 q0 = *(const float2*)(Rb + (long long)r0 * NHW + n);
                    float2 q1 = *(const float2*)(Rb + (long long)r1 * NHW + n);
                    v0.x += q0.x; v0.y += q0.y; v1.x += q1.x; v1.y += q1.y;
                }
                *(float2*)(Cb + (long long)r0 * NHW + n) = v0;
                *(float2*)(Cb + (long long)r1 * NHW + n) = v1;
            }
        }
    }
}

// ---------------- GroupNorm stats ----------------
__global__ __launch_bounds__(256) void gn_stats(const float* __restrict__ x,
                                                float* __restrict__ stats)
{
    __shared__ float sred[16];
    int b = blockIdx.x >> 5, g = blockIdx.x & 31;
    const float4* xp = reinterpret_cast<const float4*>(x + ((size_t)b * NC + g * 16) * NHW);
    const int N4 = 16 * NHW / 4;
    float s = 0.f, s2 = 0.f;
    for (int i = threadIdx.x; i < N4; i += 256) {
        float4 v = xp[i];
        s  += v.x + v.y + v.z + v.w;
        s2 += v.x * v.x + v.y * v.y + v.z * v.z + v.w * v.w;
    }
    #pragma unroll
    for (int o = 16; o > 0; o >>= 1) {
        s  += __shfl_xor_sync(0xffffffffu, s,  o);
        s2 += __shfl_xor_sync(0xffffffffu, s2, o);
    }
    int warp = threadIdx.x >> 5, lane = threadIdx.x & 31;
    if (lane == 0) { sred[warp] = s; sred[8 + warp] = s2; }
    __syncthreads();
    if (threadIdx.x == 0) {
        float ts = 0.f, ts2 = 0.f;
        #pragma unroll
        for (int wi = 0; wi < 8; wi++) { ts += sred[wi]; ts2 += sred[8 + wi]; }
        const float invn = 1.0f / (16 * NHW);
        float mean = ts * invn;
        float var  = ts2 * invn - mean * mean;
        stats[(b * 32 + g) * 2 + 0] = mean;
        stats[(b * 32 + g) * 2 + 1] = rsqrtf(var + 1e-5f);
    }
}

// ---------------- launch ----------------
extern "C" void kernel_launch(void* const* d_in, const int* in_sizes, int n_in,
                              void* d_out, int out_size)
{
    const float* x      = (const float*)d_in[0];
    const float* gamma  = (const float*)d_in[1];
    const float* beta   = (const float*)d_in[2];
    const float* qkv_w  = (const float*)d_in[3];
    const float* qkv_b  = (const float*)d_in[4];
    const float* proj_w = (const float*)d_in[5];
    const float* proj_b = (const float*)d_in[6];
    float* out = (float*)d_out;

    float *qkv, *S, *H, *stats;
    cudaGetSymbolAddress((void**)&qkv,   g_qkv);
    cudaGetSymbolAddress((void**)&S,     g_S);
    cudaGetSymbolAddress((void**)&H,     g_H);
    cudaGetSymbolAddress((void**)&stats, g_stats);

    cudaFuncSetAttribute(tc_gemm<0, false, true,  true >, cudaFuncAttributeMaxDynamicSharedMemorySize, SMEMB);
    cudaFuncSetAttribute(tc_gemm<1, true,  true,  false>, cudaFuncAttributeMaxDynamicSharedMemorySize, SMEMB);
    cudaFuncSetAttribute(tc_gemm<2, false, false, false>, cudaFuncAttributeMaxDynamicSharedMemorySize, SMEMB);
    cudaFuncSetAttribute(tc_gemm<3, false, true,  false>, cudaFuncAttributeMaxDynamicSharedMemorySize, SMEMB);

    const long long s3  = 3LL * CHW;
    const long long sSS = (long long)NHW * NHW;
    const float attn_scale = 1.0f / sqrtf((float)NC);

    // 1) GroupNorm stats (normalization fused into QKV loader)
    gn_stats<<<NB * 32, 256>>>(x, stats);

    // 2) QKV = W @ gn(x):  M=1536, N=1024, K=512.  B = x (trans + GN fused)
    tc_gemm<0, false, true, true><<<dim3(8, 12, NB), 256, SMEMB>>>(
        qkv_w, 0LL, NC, x, (long long)CHW, NHW, NC,
        qkv, s3, qkv_b, nullptr, gamma, beta, stats, 1.0f);

    // 3) S = softmax32(alpha * Q^T K): M=N=1024, K=512. A=Q, B=K (both trans)
    tc_gemm<1, true, true, false><<<dim3(8, 8, NB), 256, SMEMB>>>(
        qkv, s3, NHW, qkv + CHW, s3, NHW, NC,
        S, sSS, nullptr, nullptr, nullptr, nullptr, nullptr, attn_scale);

    // 4) H[c][p] = sum_q V[c][q] P[p][q]: M=512, N=1024, K=1024 (both direct)
    tc_gemm<2, false, false, false><<<dim3(8, 4, NB), 256, SMEMB>>>(
        qkv + 2LL * CHW, s3, NHW, S, sSS, NHW, NHW,
        H, (long long)CHW, nullptr, nullptr, nullptr, nullptr, nullptr, 1.0f);

    // 5) out = x + proj_w @ H + proj_b: M=512, N=1024, K=512. B = H (trans)
    tc_gemm<3, false, true, false><<<dim3(8, 4, NB), 256, SMEMB>>>(
        proj_w, 0LL, NC, H, (long long)CHW, NHW, NC,
        out, (long long)CHW, proj_b, x, nullptr, nullptr, nullptr, 1.0f);
}

// round 6
// speedup vs baseline: 2.5025x; 1.2050x over previous
#include <cuda_runtime.h>
#include <cuda_bf16.h>
#include <math.h>
#include <stdint.h>

#define NB   32
#define NC   512
#define NHW  1024
#define CHW  (NC * NHW)

// ---------------- persistent scratch (hi/lo bf16 split operands) ----------------
__device__ __nv_bfloat16 g_qkvh[(size_t)NB * 3 * CHW];
__device__ __nv_bfloat16 g_qkvl[(size_t)NB * 3 * CHW];
__device__ __nv_bfloat16 g_hinh[(size_t)NB * CHW];
__device__ __nv_bfloat16 g_hinl[(size_t)NB * CHW];
__device__ __nv_bfloat16 g_Ph[(size_t)NB * NHW * NHW];
__device__ __nv_bfloat16 g_Pl[(size_t)NB * NHW * NHW];
__device__ __nv_bfloat16 g_Hh[(size_t)NB * CHW];
__device__ __nv_bfloat16 g_Hl[(size_t)NB * CHW];
__device__ __nv_bfloat16 g_wqh[1536 * NC], g_wql[1536 * NC];
__device__ __nv_bfloat16 g_wph[NC * NC],   g_wpl[NC * NC];
__device__ float g_stats[NB * 32 * 2];

// ---------------- PTX helpers (baseline sm_80-era ISA only) ----------------
__device__ __forceinline__ uint32_t smem_u32(const void* p) {
    uint32_t a;
    asm("{ .reg .u64 t; cvta.to.shared.u64 t, %1; cvt.u32.u64 %0, t; }" : "=r"(a) : "l"(p));
    return a;
}
#define LDSM4(R, a) \
    asm volatile("ldmatrix.sync.aligned.m8n8.x4.shared.b16 {%0,%1,%2,%3}, [%4];" \
        : "=r"((R)[0]), "=r"((R)[1]), "=r"((R)[2]), "=r"((R)[3]) : "r"(a))
#define LDSM4T(R, a) \
    asm volatile("ldmatrix.sync.aligned.m8n8.x4.trans.shared.b16 {%0,%1,%2,%3}, [%4];" \
        : "=r"((R)[0]), "=r"((R)[1]), "=r"((R)[2]), "=r"((R)[3]) : "r"(a))
#define CP16(d, s) \
    asm volatile("cp.async.cg.shared.global [%0], [%1], 16;" :: "r"(d), "l"(s))
#define CP_COMMIT() asm volatile("cp.async.commit_group;" ::: "memory")
#define CP_WAIT0()  asm volatile("cp.async.wait_group 0;" ::: "memory")

__device__ __forceinline__ void mma16816(float* d, const uint32_t* a, uint32_t b0, uint32_t b1) {
    asm volatile("mma.sync.aligned.m16n8k16.row.col.f32.bf16.bf16.f32 "
                 "{%0,%1,%2,%3}, {%4,%5,%6,%7}, {%8,%9}, {%0,%1,%2,%3};"
                 : "+f"(d[0]), "+f"(d[1]), "+f"(d[2]), "+f"(d[3])
                 : "r"(a[0]), "r"(a[1]), "r"(a[2]), "r"(a[3]), "r"(b0), "r"(b1));
}

// fp32 pair -> bf16 hi pair + lo pair, store to two arrays
__device__ __forceinline__ void store_pair(__nv_bfloat16* H, __nv_bfloat16* L,
                                           long long off, float2 v) {
    __nv_bfloat162 h = __float22bfloat162_rn(v);
    float2 hf = __bfloat1622float2(h);
    __nv_bfloat162 lo = __float22bfloat162_rn(make_float2(v.x - hf.x, v.y - hf.y));
    *reinterpret_cast<__nv_bfloat162*>(H + off) = h;
    *reinterpret_cast<__nv_bfloat162*>(L + off) = lo;
}

// smem: 2 stages x (AH | AL | BH | BL)
//   direct tile: 128 rows x 80B (64B = 32 bf16 k-values + 16B pad)
//   trans  tile:  32 krows x 272B (256B = 128 bf16 mn-values + 16B pad)
#define SLOT   10240
#define STAGEB 40960
#define SMEMB  81920

// EPI: 0=QKV(+bias, bf16 out), 1=S(alpha + fused 32-wide softmax, bf16 out),
//      2=H(bf16 out), 3=proj(+bias+residual, fp32 out)
template<int EPI, bool TA, bool TB>
__global__ __launch_bounds__(256, 2)
void tc_gemm(const __nv_bfloat16* __restrict__ Ah_, const __nv_bfloat16* __restrict__ Al_,
             long long sAb, int lda,
             const __nv_bfloat16* __restrict__ Bh_, const __nv_bfloat16* __restrict__ Bl_,
             long long sBb, int ldb,
             int Ktot,
             float* __restrict__ Cf, __nv_bfloat16* __restrict__ Ch, __nv_bfloat16* __restrict__ Cl,
             long long sCb,
             const float* __restrict__ bias, const float* __restrict__ res, float alpha)
{
    extern __shared__ char sm[];
    const int tid = threadIdx.x, l = tid & 31, wid = tid >> 5;
    const int bz = blockIdx.z;
    const int m0 = blockIdx.y * 128, n0 = blockIdx.x * 128;
    const int wm = (wid >> 2) * 64, wn = (wid & 3) * 32;

    const __nv_bfloat16* Agh = Ah_ + bz * sAb + (TA ? (long long)m0 : (long long)m0 * lda);
    const __nv_bfloat16* Agl = Al_ + bz * sAb + (TA ? (long long)m0 : (long long)m0 * lda);
    const __nv_bfloat16* Bgh = Bh_ + bz * sBb + (TB ? (long long)n0 : (long long)n0 * ldb);
    const __nv_bfloat16* Bgl = Bl_ + bz * sBb + (TB ? (long long)n0 : (long long)n0 * ldb);

    const uint32_t smb = smem_u32(sm);

    // ldmatrix fragment addressing (same layout as proven R5 tiles)
    const uint32_t dOff = (uint32_t)((l & 15) * 80 + (l >> 4) * 16);
    const uint32_t tOff = (uint32_t)(((l & 7) + ((l >> 4) << 3)) * 272 + ((l >> 3) & 1) * 16);
    const uint32_t aFragBase = TA ? (uint32_t)(wm * 2 + tOff) : (uint32_t)(wm * 80 + dOff);
    const uint32_t bFragBase = TB ? (uint32_t)(wn * 2 + tOff) : (uint32_t)(wn * 80 + dOff);
    const uint32_t aMT = TA ? 32u : 1280u;
    const uint32_t bG  = TB ? 32u : 1280u;
    const uint32_t aH  = TA ? 4352u : 32u;
    const uint32_t bH  = TB ? 4352u : 32u;

    float acc[4][4][4];
    #pragma unroll
    for (int i = 0; i < 4; i++)
        #pragma unroll
        for (int j = 0; j < 4; j++)
            #pragma unroll
            for (int k = 0; k < 4; k++) acc[i][j][k] = 0.f;

    auto ISSUE = [&](int s, int buf) {
        uint32_t st = smb + buf * STAGEB;
        int k0 = s * 32;
        // ---- A ----
        if (TA) {
            #pragma unroll
            for (int i = 0; i < 2; i++) {
                int idx = tid + i * 256;
                int row = idx >> 4, ch = idx & 15;
                uint32_t d = st + row * 272 + ch * 16;
                CP16(d,        Agh + (long long)(k0 + row) * lda + ch * 8);
                CP16(d + SLOT, Agl + (long long)(k0 + row) * lda + ch * 8);
            }
        } else {
            #pragma unroll
            for (int i = 0; i < 2; i++) {
                int idx = tid + i * 256;
                int row = idx >> 2, ch = idx & 3;
                uint32_t d = st + row * 80 + ch * 16;
                CP16(d,        Agh + (long long)row * lda + k0 + ch * 8);
                CP16(d + SLOT, Agl + (long long)row * lda + k0 + ch * 8);
            }
        }
        // ---- B ----
        uint32_t sb2 = st + 2 * SLOT;
        if (TB) {
            #pragma unroll
            for (int i = 0; i < 2; i++) {
                int idx = tid + i * 256;
                int row = idx >> 4, ch = idx & 15;
                uint32_t d = sb2 + row * 272 + ch * 16;
                CP16(d,        Bgh + (long long)(k0 + row) * ldb + ch * 8);
                CP16(d + SLOT, Bgl + (long long)(k0 + row) * ldb + ch * 8);
            }
        } else {
            #pragma unroll
            for (int i = 0; i < 2; i++) {
                int idx = tid + i * 256;
                int row = idx >> 2, ch = idx & 3;
                uint32_t d = sb2 + row * 80 + ch * 16;
                CP16(d,        Bgh + (long long)row * ldb + k0 + ch * 8);
                CP16(d + SLOT, Bgl + (long long)row * ldb + k0 + ch * 8);
            }
        }
    };

    auto COMPUTE = [&](int buf) {
        uint32_t base = smb + buf * STAGEB;
        #pragma unroll
        for (int h = 0; h < 2; h++) {
            uint32_t BhF[2][4], BlF[2][4];
            #pragma unroll
            for (int g = 0; g < 2; g++) {
                uint32_t bd = base + 2 * SLOT + bFragBase + g * bG + h * bH;
                if (TB) { LDSM4T(BhF[g], bd); LDSM4T(BlF[g], bd + SLOT); }
                else    { LDSM4 (BhF[g], bd); LDSM4 (BlF[g], bd + SLOT); }
            }
            #pragma unroll
            for (int mt = 0; mt < 4; mt++) {
                uint32_t AhF[4], AlF[4];
                uint32_t ad = base + aFragBase + mt * aMT + h * aH;
                if (TA) { LDSM4T(AhF, ad); LDSM4T(AlF, ad + SLOT); }
                else    { LDSM4 (AhF, ad); LDSM4 (AlF, ad + SLOT); }
                #pragma unroll
                for (int nt = 0; nt < 4; nt++) {
                    float* d = acc[mt][nt];
                    uint32_t b0h = BhF[nt >> 1][nt & 1], b1h = BhF[nt >> 1][2 + (nt & 1)];
                    uint32_t b0l = BlF[nt >> 1][nt & 1], b1l = BlF[nt >> 1][2 + (nt & 1)];
                    mma16816(d, AhF, b0h, b1h);
                    mma16816(d, AhF, b0l, b1l);
                    mma16816(d, AlF, b0h, b1h);
                }
            }
        }
    };

    // ---- pipeline: double-buffered cp.async, one sync per stage ----
    const int NS = Ktot / 32;
    ISSUE(0, 0); CP_COMMIT();
    for (int s = 0; s < NS; s++) {
        CP_WAIT0();
        __syncthreads();
        if (s + 1 < NS) { ISSUE(s + 1, (s + 1) & 1); CP_COMMIT(); }
        COMPUTE(s & 1);
    }

    // ---- epilogue ----
    if (EPI == 1) {
        __nv_bfloat16* ChB = Ch + (long long)bz * sCb;
        __nv_bfloat16* ClB = Cl + (long long)bz * sCb;
        #pragma unroll
        for (int mt = 0; mt < 4; mt++) {
            int r0 = m0 + wm + mt * 16 + (l >> 2);
            int r1 = r0 + 8;
            float vl[8], vh[8];
            #pragma unroll
            for (int nt = 0; nt < 4; nt++) {
                vl[2 * nt]     = acc[mt][nt][0] * alpha;
                vl[2 * nt + 1] = acc[mt][nt][1] * alpha;
                vh[2 * nt]     = acc[mt][nt][2] * alpha;
                vh[2 * nt + 1] = acc[mt][nt][3] * alpha;
            }
            float m_lo = vl[0], m_hi = vh[0];
            #pragma unroll
            for (int j = 1; j < 8; j++) { m_lo = fmaxf(m_lo, vl[j]); m_hi = fmaxf(m_hi, vh[j]); }
            m_lo = fmaxf(m_lo, __shfl_xor_sync(0xffffffffu, m_lo, 1));
            m_lo = fmaxf(m_lo, __shfl_xor_sync(0xffffffffu, m_lo, 2));
            m_hi = fmaxf(m_hi, __shfl_xor_sync(0xffffffffu, m_hi, 1));
            m_hi = fmaxf(m_hi, __shfl_xor_sync(0xffffffffu, m_hi, 2));
            float s_lo = 0.f, s_hi = 0.f;
            #pragma unroll
            for (int j = 0; j < 8; j++) {
                vl[j] = __expf(vl[j] - m_lo); s_lo += vl[j];
                vh[j] = __expf(vh[j] - m_hi); s_hi += vh[j];
            }
            s_lo += __shfl_xor_sync(0xffffffffu, s_lo, 1);
            s_lo += __shfl_xor_sync(0xffffffffu, s_lo, 2);
            s_hi += __shfl_xor_sync(0xffffffffu, s_hi, 1);
            s_hi += __shfl_xor_sync(0xffffffffu, s_hi, 2);
            float i_lo = 1.0f / s_lo, i_hi = 1.0f / s_hi;
            #pragma unroll
            for (int nt = 0; nt < 4; nt++) {
                int n = n0 + wn + nt * 8 + (l & 3) * 2;
                store_pair(ChB, ClB, (long long)r0 * NHW + n,
                           make_float2(vl[2 * nt] * i_lo, vl[2 * nt + 1] * i_lo));
                store_pair(ChB, ClB, (long long)r1 * NHW + n,
                           make_float2(vh[2 * nt] * i_hi, vh[2 * nt + 1] * i_hi));
            }
        }
    } else if (EPI == 3) {
        float* Cb = Cf + (long long)bz * sCb;
        const float* Rb = res + (long long)bz * sCb;
        #pragma unroll
        for (int mt = 0; mt < 4; mt++) {
            int r0 = m0 + wm + mt * 16 + (l >> 2);
            int r1 = r0 + 8;
            float b0v = bias[r0], b1v = bias[r1];
            #pragma unroll
            for (int nt = 0; nt < 4; nt++) {
                int n = n0 + wn + nt * 8 + (l & 3) * 2;
                float2 q0 = *(const float2*)(Rb + (long long)r0 * NHW + n);
                float2 q1 = *(const float2*)(Rb + (long long)r1 * NHW + n);
                *(float2*)(Cb + (long long)r0 * NHW + n) =
                    make_float2(acc[mt][nt][0] + b0v + q0.x, acc[mt][nt][1] + b0v + q0.y);
                *(float2*)(Cb + (long long)r1 * NHW + n) =
                    make_float2(acc[mt][nt][2] + b1v + q1.x, acc[mt][nt][3] + b1v + q1.y);
            }
        }
    } else {
        __nv_bfloat16* ChB = Ch + (long long)bz * sCb;
        __nv_bfloat16* ClB = Cl + (long long)bz * sCb;
        #pragma unroll
        for (int mt = 0; mt < 4; mt++) {
            int r0 = m0 + wm + mt * 16 + (l >> 2);
            int r1 = r0 + 8;
            float b0v = 0.f, b1v = 0.f;
            if (EPI == 0) { b0v = bias[r0]; b1v = bias[r1]; }
            #pragma unroll
            for (int nt = 0; nt < 4; nt++) {
                int n = n0 + wn + nt * 8 + (l & 3) * 2;
                store_pair(ChB, ClB, (long long)r0 * NHW + n,
                           make_float2(acc[mt][nt][0] + b0v, acc[mt][nt][1] + b0v));
                store_pair(ChB, ClB, (long long)r1 * NHW + n,
                           make_float2(acc[mt][nt][2] + b1v, acc[mt][nt][3] + b1v));
            }
        }
    }
}

// ---------------- GroupNorm stats ----------------
__global__ __launch_bounds__(256) void gn_stats(const float* __restrict__ x,
                                                float* __restrict__ stats)
{
    __shared__ float sred[16];
    int b = blockIdx.x >> 5, g = blockIdx.x & 31;
    const float4* xp = reinterpret_cast<const float4*>(x + ((size_t)b * NC + g * 16) * NHW);
    const int N4 = 16 * NHW / 4;
    float s = 0.f, s2 = 0.f;
    for (int i = threadIdx.x; i < N4; i += 256) {
        float4 v = xp[i];
        s  += v.x + v.y + v.z + v.w;
        s2 += v.x * v.x + v.y * v.y + v.z * v.z + v.w * v.w;
    }
    #pragma unroll
    for (int o = 16; o > 0; o >>= 1) {
        s  += __shfl_xor_sync(0xffffffffu, s,  o);
        s2 += __shfl_xor_sync(0xffffffffu, s2, o);
    }
    int warp = threadIdx.x >> 5, lane = threadIdx.x & 31;
    if (lane == 0) { sred[warp] = s; sred[8 + warp] = s2; }
    __syncthreads();
    if (threadIdx.x == 0) {
        float ts = 0.f, ts2 = 0.f;
        #pragma unroll
        for (int wi = 0; wi < 8; wi++) { ts += sred[wi]; ts2 += sred[8 + wi]; }
        const float invn = 1.0f / (16 * NHW);
        float mean = ts * invn;
        float var  = ts2 * invn - mean * mean;
        stats[(b * 32 + g) * 2 + 0] = mean;
        stats[(b * 32 + g) * 2 + 1] = rsqrtf(var + 1e-5f);
    }
}

// ---------------- GroupNorm normalize + bf16 hi/lo split (natural [c][p] layout) ----------------
__global__ __launch_bounds__(256) void gn_split(
    const float* __restrict__ x, const float* __restrict__ gamma,
    const float* __restrict__ beta, const float* __restrict__ stats,
    __nv_bfloat16* __restrict__ yh, __nv_bfloat16* __restrict__ yl)
{
    int b = blockIdx.y;
    long long i4 = (long long)blockIdx.x * 256 + threadIdx.x;   // float4 index in batch
    int c = (int)((i4 * 4) >> 10);
    float mean = stats[(b * 32 + (c >> 4)) * 2 + 0];
    float rstd = stats[(b * 32 + (c >> 4)) * 2 + 1];
    float gm = gamma[c] * rstd;
    float gb = beta[c] - mean * gm;
    float4 v = reinterpret_cast<const float4*>(x + (size_t)b * CHW)[i4];
    v.x = v.x * gm + gb; v.y = v.y * gm + gb;
    v.z = v.z * gm + gb; v.w = v.w * gm + gb;
    __nv_bfloat162 h0 = __float22bfloat162_rn(make_float2(v.x, v.y));
    __nv_bfloat162 h1 = __float22bfloat162_rn(make_float2(v.z, v.w));
    float2 f0 = __bfloat1622float2(h0), f1 = __bfloat1622float2(h1);
    __nv_bfloat162 l0 = __float22bfloat162_rn(make_float2(v.x - f0.x, v.y - f0.y));
    __nv_bfloat162 l1 = __float22bfloat162_rn(make_float2(v.z - f1.x, v.w - f1.y));
    __nv_bfloat162* ph = reinterpret_cast<__nv_bfloat162*>(yh + (size_t)b * CHW);
    __nv_bfloat162* pl = reinterpret_cast<__nv_bfloat162*>(yl + (size_t)b * CHW);
    ph[i4 * 2] = h0; ph[i4 * 2 + 1] = h1;
    pl[i4 * 2] = l0; pl[i4 * 2 + 1] = l1;
}

// ---------------- weight hi/lo split ----------------
__global__ __launch_bounds__(256) void wsplit(const float* __restrict__ w,
                                              __nv_bfloat16* __restrict__ wh,
                                              __nv_bfloat16* __restrict__ wl, int n4)
{
    int i = blockIdx.x * 256 + threadIdx.x;
    if (i >= n4) return;
    float4 v = reinterpret_cast<const float4*>(w)[i];
    __nv_bfloat162 h0 = __float22bfloat162_rn(make_float2(v.x, v.y));
    __nv_bfloat162 h1 = __float22bfloat162_rn(make_float2(v.z, v.w));
    float2 f0 = __bfloat1622float2(h0), f1 = __bfloat1622float2(h1);
    __nv_bfloat162 l0 = __float22bfloat162_rn(make_float2(v.x - f0.x, v.y - f0.y));
    __nv_bfloat162 l1 = __float22bfloat162_rn(make_float2(v.z - f1.x, v.w - f1.y));
    reinterpret_cast<__nv_bfloat162*>(wh)[i * 2]     = h0;
    reinterpret_cast<__nv_bfloat162*>(wh)[i * 2 + 1] = h1;
    reinterpret_cast<__nv_bfloat162*>(wl)[i * 2]     = l0;
    reinterpret_cast<__nv_bfloat162*>(wl)[i * 2 + 1] = l1;
}

// ---------------- launch ----------------
extern "C" void kernel_launch(void* const* d_in, const int* in_sizes, int n_in,
                              void* d_out, int out_size)
{
    const float* x      = (const float*)d_in[0];
    const float* gamma  = (const float*)d_in[1];
    const float* beta   = (const float*)d_in[2];
    const float* qkv_w  = (const float*)d_in[3];
    const float* qkv_b  = (const float*)d_in[4];
    const float* proj_w = (const float*)d_in[5];
    const float* proj_b = (const float*)d_in[6];
    float* out = (float*)d_out;

    __nv_bfloat16 *qkvh, *qkvl, *hinh, *hinl, *Ph, *Pl, *Hh, *Hl, *wqh, *wql, *wph, *wpl;
    float* stats;
    cudaGetSymbolAddress((void**)&qkvh, g_qkvh);
    cudaGetSymbolAddress((void**)&qkvl, g_qkvl);
    cudaGetSymbolAddress((void**)&hinh, g_hinh);
    cudaGetSymbolAddress((void**)&hinl, g_hinl);
    cudaGetSymbolAddress((void**)&Ph,   g_Ph);
    cudaGetSymbolAddress((void**)&Pl,   g_Pl);
    cudaGetSymbolAddress((void**)&Hh,   g_Hh);
    cudaGetSymbolAddress((void**)&Hl,   g_Hl);
    cudaGetSymbolAddress((void**)&wqh,  g_wqh);
    cudaGetSymbolAddress((void**)&wql,  g_wql);
    cudaGetSymbolAddress((void**)&wph,  g_wph);
    cudaGetSymbolAddress((void**)&wpl,  g_wpl);
    cudaGetSymbolAddress((void**)&stats, g_stats);

    cudaFuncSetAttribute(tc_gemm<0, false, true >, cudaFuncAttributeMaxDynamicSharedMemorySize, SMEMB);
    cudaFuncSetAttribute(tc_gemm<1, true,  true >, cudaFuncAttributeMaxDynamicSharedMemorySize, SMEMB);
    cudaFuncSetAttribute(tc_gemm<2, false, false>, cudaFuncAttributeMaxDynamicSharedMemorySize, SMEMB);
    cudaFuncSetAttribute(tc_gemm<3, false, true >, cudaFuncAttributeMaxDynamicSharedMemorySize, SMEMB);

    const long long s3  = 3LL * CHW;
    const long long sSS = (long long)NHW * NHW;
    const float attn_scale = 1.0f / sqrtf((float)NC);

    // 1) operand prep
    gn_stats<<<NB * 32, 256>>>(x, stats);
    wsplit<<<(1536 * NC / 4 + 255) / 256, 256>>>(qkv_w, wqh, wql, 1536 * NC / 4);
    wsplit<<<(NC * NC / 4 + 255) / 256, 256>>>(proj_w, wph, wpl, NC * NC / 4);
    gn_split<<<dim3(CHW / 1024, NB), 256>>>(x, gamma, beta, stats, hinh, hinl);

    // 2) QKV = W @ gn(x): M=1536, N=1024, K=512.  A direct, B trans
    tc_gemm<0, false, true><<<dim3(8, 12, NB), 256, SMEMB>>>(
        wqh, wql, 0LL, NC, hinh, hinl, (long long)CHW, NHW, NC,
        nullptr, qkvh, qkvl, s3, qkv_b, nullptr, 1.0f);

    // 3) S = softmax32(alpha * Q^T K): M=N=1024, K=512. Both trans
    tc_gemm<1, true, true><<<dim3(8, 8, NB), 256, SMEMB>>>(
        qkvh, qkvl, s3, NHW, qkvh + CHW, qkvl + CHW, s3, NHW, NC,
        nullptr, Ph, Pl, sSS, nullptr, nullptr, attn_scale);

    // 4) H[c][p] = sum_q V[c][q] P[p][q]: M=512, N=1024, K=1024. Both direct
    tc_gemm<2, false, false><<<dim3(8, 4, NB), 256, SMEMB>>>(
        qkvh + 2LL * CHW, qkvl + 2LL * CHW, s3, NHW, Ph, Pl, sSS, NHW, NHW,
        nullptr, Hh, Hl, (long long)CHW, nullptr, nullptr, 1.0f);

    // 5) out = x + proj_w @ H + proj_b: M=512, N=1024, K=512. A direct, B trans
    tc_gemm<3, false, true><<<dim3(8, 4, NB), 256, SMEMB>>>(
        wph, wpl, 0LL, NC, Hh, Hl, (long long)CHW, NHW, NC,
        out, nullptr, nullptr, (long long)CHW, proj_b, x, 1.0f);
}

// round 7
// speedup vs baseline: 2.8016x; 1.1195x over previous
#include <cuda_runtime.h>
#include <cuda_bf16.h>
#include <math.h>
#include <stdint.h>

#define NB   32
#define NC   512
#define NHW  1024
#define CHW  (NC * NHW)

// ---------------- persistent scratch (hi/lo bf16 split operands) ----------------
__device__ __nv_bfloat16 g_qkvh[(size_t)NB * 3 * CHW];
__device__ __nv_bfloat16 g_qkvl[(size_t)NB * 3 * CHW];
__device__ __nv_bfloat16 g_hinh[(size_t)NB * CHW];
__device__ __nv_bfloat16 g_hinl[(size_t)NB * CHW];
__device__ __nv_bfloat16 g_Ph[(size_t)NB * NHW * NHW];
__device__ __nv_bfloat16 g_Pl[(size_t)NB * NHW * NHW];
__device__ __nv_bfloat16 g_Hh[(size_t)NB * CHW];
__device__ __nv_bfloat16 g_Hl[(size_t)NB * CHW];
__device__ __nv_bfloat16 g_wqh[1536 * NC], g_wql[1536 * NC];
__device__ __nv_bfloat16 g_wph[NC * NC],   g_wpl[NC * NC];
__device__ float g_stats[NB * 32 * 2];

// ---------------- PTX helpers (baseline sm_80-era ISA only) ----------------
__device__ __forceinline__ uint32_t smem_u32(const void* p) {
    uint32_t a;
    asm("{ .reg .u64 t; cvta.to.shared.u64 t, %1; cvt.u32.u64 %0, t; }" : "=r"(a) : "l"(p));
    return a;
}
#define LDSM4(R, a) \
    asm volatile("ldmatrix.sync.aligned.m8n8.x4.shared.b16 {%0,%1,%2,%3}, [%4];" \
        : "=r"((R)[0]), "=r"((R)[1]), "=r"((R)[2]), "=r"((R)[3]) : "r"(a))
#define LDSM4T(R, a) \
    asm volatile("ldmatrix.sync.aligned.m8n8.x4.trans.shared.b16 {%0,%1,%2,%3}, [%4];" \
        : "=r"((R)[0]), "=r"((R)[1]), "=r"((R)[2]), "=r"((R)[3]) : "r"(a))
#define CP16(d, s) \
    asm volatile("cp.async.cg.shared.global [%0], [%1], 16;" :: "r"(d), "l"(s))
#define CP_COMMIT() asm volatile("cp.async.commit_group;" ::: "memory")
#define CP_WAIT1()  asm volatile("cp.async.wait_group 1;" ::: "memory")
#define CP_WAIT0()  asm volatile("cp.async.wait_group 0;" ::: "memory")

__device__ __forceinline__ void mma16816(float* d, const uint32_t* a, uint32_t b0, uint32_t b1) {
    asm volatile("mma.sync.aligned.m16n8k16.row.col.f32.bf16.bf16.f32 "
                 "{%0,%1,%2,%3}, {%4,%5,%6,%7}, {%8,%9}, {%0,%1,%2,%3};"
                 : "+f"(d[0]), "+f"(d[1]), "+f"(d[2]), "+f"(d[3])
                 : "r"(a[0]), "r"(a[1]), "r"(a[2]), "r"(a[3]), "r"(b0), "r"(b1));
}

__device__ __forceinline__ void store_pair(__nv_bfloat16* H, __nv_bfloat16* L,
                                           long long off, float2 v) {
    __nv_bfloat162 h = __float22bfloat162_rn(v);
    float2 hf = __bfloat1622float2(h);
    __nv_bfloat162 lo = __float22bfloat162_rn(make_float2(v.x - hf.x, v.y - hf.y));
    *reinterpret_cast<__nv_bfloat162*>(H + off) = h;
    *reinterpret_cast<__nv_bfloat162*>(L + off) = lo;
}

// smem: 3 stages x (AH | AL | BH | BL), swizzled tiles, no padding
//   direct tile: 128 rows x 64B,  chunk(16B) swizzle: c ^= (row>>1)&3
//   trans  tile:  32 rows x 256B, chunk(16B) swizzle: c ^= row&7
#define SLOT   8192
#define STAGEB 32768
#define SMEMB  98304

// EPI: 0=QKV(+bias, bf16 out), 1=S(alpha + fused 32-wide softmax, bf16 out),
//      2=H(bf16 out), 3=proj(+bias+residual, fp32 out)
template<int EPI, bool TA, bool TB>
__global__ __launch_bounds__(256, 2)
void tc_gemm(const __nv_bfloat16* __restrict__ Ah_, const __nv_bfloat16* __restrict__ Al_,
             long long sAb, int lda,
             const __nv_bfloat16* __restrict__ Bh_, const __nv_bfloat16* __restrict__ Bl_,
             long long sBb, int ldb,
             int Ktot,
             float* __restrict__ Cf, __nv_bfloat16* __restrict__ Ch, __nv_bfloat16* __restrict__ Cl,
             long long sCb,
             const float* __restrict__ bias, const float* __restrict__ res, float alpha)
{
    extern __shared__ char sm[];
    const int tid = threadIdx.x, l = tid & 31, wid = tid >> 5;
    const int bz = blockIdx.z;
    const int m0 = blockIdx.y * 128, n0 = blockIdx.x * 128;
    const int wm = (wid >> 2) * 64, wn = (wid & 3) * 32;

    const __nv_bfloat16* Agh = Ah_ + bz * sAb + (TA ? (long long)m0 : (long long)m0 * lda);
    const __nv_bfloat16* Agl = Al_ + bz * sAb + (TA ? (long long)m0 : (long long)m0 * lda);
    const __nv_bfloat16* Bgh = Bh_ + bz * sBb + (TB ? (long long)n0 : (long long)n0 * ldb);
    const __nv_bfloat16* Bgl = Bl_ + bz * sBb + (TB ? (long long)n0 : (long long)n0 * ldb);

    const uint32_t smb = smem_u32(sm);

    // --- fragment lane bases (swizzled) ---
    // direct: addr(row=(l&15)+16mt(+wrow), chunk=(l>>4)+2h) = lanebase + rowoffs ^ (h<<5)
    const uint32_t rdir = (uint32_t)(l & 15);
    const uint32_t dirLane = rdir * 64 + (((((rdir >> 1) & 3)) ^ (uint32_t)(l >> 4)) << 4);
    // trans: addr(krow=rr+16h, mnchunk) = lanebase ^ (mnbits<<4), lanebase holds (l&7)^g8 swz
    const uint32_t rr = (uint32_t)((l & 7) + ((l >> 4) << 3));
    const uint32_t g8 = (uint32_t)((l >> 3) & 1);
    const uint32_t trLane = rr * 256 + ((((uint32_t)(l & 7)) ^ g8) << 4);

    const uint32_t aLane = TA ? (trLane ^ (uint32_t)(wm * 2)) : (dirLane + wm * 64);
    const uint32_t bLane = TB ? (trLane ^ (uint32_t)(wn * 2)) : (dirLane + wn * 64);
    const uint32_t aMT = TA ? 0u : 1024u;       // additive per-mt (direct); trans uses XOR mt<<5
    const uint32_t bG  = TB ? 0u : 1024u;
    const uint32_t aH  = TA ? 4096u : 0u;       // additive per-h (trans); direct uses XOR h<<5
    const uint32_t bH  = TB ? 4096u : 0u;

    float acc[4][4][4];
    #pragma unroll
    for (int i = 0; i < 4; i++)
        #pragma unroll
        for (int j = 0; j < 4; j++)
            #pragma unroll
            for (int k = 0; k < 4; k++) acc[i][j][k] = 0.f;

    auto ISSUE = [&](int s, int buf) {
        uint32_t st = smb + buf * STAGEB;
        int k0 = s * 32;
        // ---- A ----
        if (TA) {
            #pragma unroll
            for (int i = 0; i < 2; i++) {
                int idx = tid + i * 256;
                uint32_t row = (uint32_t)idx >> 4, ch = (uint32_t)idx & 15;
                uint32_t d = st + row * 256 + ((ch ^ (row & 7)) << 4);
                CP16(d,        Agh + (long long)(k0 + (int)row) * lda + ch * 8);
                CP16(d + SLOT, Agl + (long long)(k0 + (int)row) * lda + ch * 8);
            }
        } else {
            #pragma unroll
            for (int i = 0; i < 2; i++) {
                int idx = tid + i * 256;
                uint32_t row = (uint32_t)idx >> 2, ch = (uint32_t)idx & 3;
                uint32_t d = st + row * 64 + ((ch ^ ((row >> 1) & 3)) << 4);
                CP16(d,        Agh + (long long)row * lda + k0 + ch * 8);
                CP16(d + SLOT, Agl + (long long)row * lda + k0 + ch * 8);
            }
        }
        // ---- B ----
        uint32_t sb2 = st + 2 * SLOT;
        if (TB) {
            #pragma unroll
            for (int i = 0; i < 2; i++) {
                int idx = tid + i * 256;
                uint32_t row = (uint32_t)idx >> 4, ch = (uint32_t)idx & 15;
                uint32_t d = sb2 + row * 256 + ((ch ^ (row & 7)) << 4);
                CP16(d,        Bgh + (long long)(k0 + (int)row) * ldb + ch * 8);
                CP16(d + SLOT, Bgl + (long long)(k0 + (int)row) * ldb + ch * 8);
            }
        } else {
            #pragma unroll
            for (int i = 0; i < 2; i++) {
                int idx = tid + i * 256;
                uint32_t row = (uint32_t)idx >> 2, ch = (uint32_t)idx & 3;
                uint32_t d = sb2 + row * 64 + ((ch ^ ((row >> 1) & 3)) << 4);
                CP16(d,        Bgh + (long long)row * ldb + k0 + ch * 8);
                CP16(d + SLOT, Bgl + (long long)row * ldb + k0 + ch * 8);
            }
        }
    };

    auto COMPUTE = [&](int buf) {
        uint32_t base = smb + buf * STAGEB;
        #pragma unroll
        for (int h = 0; h < 2; h++) {
            uint32_t BhF[2][4], BlF[2][4];
            #pragma unroll
            for (int g = 0; g < 2; g++) {
                uint32_t bd = base + 2 * SLOT;
                if (TB) bd += bLane + h * bH, bd ^= (uint32_t)(g << 5);
                else    bd += (bLane + g * bG), bd ^= (uint32_t)(h << 5);
                LDSM4_DISPATCH_B:
                if (TB) { LDSM4T(BhF[g], bd); LDSM4T(BlF[g], bd + SLOT); }
                else    { LDSM4 (BhF[g], bd); LDSM4 (BlF[g], bd + SLOT); }
            }
            #pragma unroll
            for (int mt = 0; mt < 4; mt++) {
                uint32_t AhF[4], AlF[4];
                uint32_t ad = base;
                if (TA) ad += aLane + h * aH, ad ^= (uint32_t)(mt << 5);
                else    ad += (aLane + mt * aMT), ad ^= (uint32_t)(h << 5);
                if (TA) { LDSM4T(AhF, ad); LDSM4T(AlF, ad + SLOT); }
                else    { LDSM4 (AhF, ad); LDSM4 (AlF, ad + SLOT); }
                #pragma unroll
                for (int nt = 0; nt < 4; nt++) {
                    float* d = acc[mt][nt];
                    uint32_t b0h = BhF[nt >> 1][nt & 1], b1h = BhF[nt >> 1][2 + (nt & 1)];
                    uint32_t b0l = BlF[nt >> 1][nt & 1], b1l = BlF[nt >> 1][2 + (nt & 1)];
                    mma16816(d, AhF, b0h, b1h);
                    mma16816(d, AhF, b0l, b1l);
                    mma16816(d, AlF, b0h, b1h);
                }
            }
        }
    };

    // ---- 3-stage cp.async pipeline ----
    const int NS = Ktot / 32;
    ISSUE(0, 0); CP_COMMIT();
    ISSUE(1, 1); CP_COMMIT();
    for (int s = 0; s < NS; s++) {
        if (s + 1 < NS) { CP_WAIT1(); } else { CP_WAIT0(); }
        __syncthreads();
        if (s + 2 < NS) {
            int b3 = s + 2; b3 = (b3 >= 3) ? (b3 % 3) : b3;
            ISSUE(s + 2, b3); CP_COMMIT();
        }
        int c3 = s % 3;
        COMPUTE(c3);
    }

    // ---- epilogue ----
    if (EPI == 1) {
        __nv_bfloat16* ChB = Ch + (long long)bz * sCb;
        __nv_bfloat16* ClB = Cl + (long long)bz * sCb;
        #pragma unroll
        for (int mt = 0; mt < 4; mt++) {
            int r0 = m0 + wm + mt * 16 + (l >> 2);
            int r1 = r0 + 8;
            float vl[8], vh[8];
            #pragma unroll
            for (int nt = 0; nt < 4; nt++) {
                vl[2 * nt]     = acc[mt][nt][0] * alpha;
                vl[2 * nt + 1] = acc[mt][nt][1] * alpha;
                vh[2 * nt]     = acc[mt][nt][2] * alpha;
                vh[2 * nt + 1] = acc[mt][nt][3] * alpha;
            }
            float m_lo = vl[0], m_hi = vh[0];
            #pragma unroll
            for (int j = 1; j < 8; j++) { m_lo = fmaxf(m_lo, vl[j]); m_hi = fmaxf(m_hi, vh[j]); }
            m_lo = fmaxf(m_lo, __shfl_xor_sync(0xffffffffu, m_lo, 1));
            m_lo = fmaxf(m_lo, __shfl_xor_sync(0xffffffffu, m_lo, 2));
            m_hi = fmaxf(m_hi, __shfl_xor_sync(0xffffffffu, m_hi, 1));
            m_hi = fmaxf(m_hi, __shfl_xor_sync(0xffffffffu, m_hi, 2));
            float s_lo = 0.f, s_hi = 0.f;
            #pragma unroll
            for (int j = 0; j < 8; j++) {
                vl[j] = __expf(vl[j] - m_lo); s_lo += vl[j];
                vh[j] = __expf(vh[j] - m_hi); s_hi += vh[j];
            }
            s_lo += __shfl_xor_sync(0xffffffffu, s_lo, 1);
            s_lo += __shfl_xor_sync(0xffffffffu, s_lo, 2);
            s_hi += __shfl_xor_sync(0xffffffffu, s_hi, 1);
            s_hi += __shfl_xor_sync(0xffffffffu, s_hi, 2);
            float i_lo = 1.0f / s_lo, i_hi = 1.0f / s_hi;
            #pragma unroll
            for (int nt = 0; nt < 4; nt++) {
                int n = n0 + wn + nt * 8 + (l & 3) * 2;
                store_pair(ChB, ClB, (long long)r0 * NHW + n,
                           make_float2(vl[2 * nt] * i_lo, vl[2 * nt + 1] * i_lo));
                store_pair(ChB, ClB, (long long)r1 * NHW + n,
                           make_float2(vh[2 * nt] * i_hi, vh[2 * nt + 1] * i_hi));
            }
        }
    } else if (EPI == 3) {
        float* Cb = Cf + (long long)bz * sCb;
        const float* Rb = res + (long long)bz * sCb;
        #pragma unroll
        for (int mt = 0; mt < 4; mt++) {
            int r0 = m0 + wm + mt * 16 + (l >> 2);
            int r1 = r0 + 8;
            float b0v = bias[r0], b1v = bias[r1];
            #pragma unroll
            for (int nt = 0; nt < 4; nt++) {
                int n = n0 + wn + nt * 8 + (l & 3) * 2;
                float2 q0 = *(const float2*)(Rb + (long long)r0 * NHW + n);
                float2 q1 = *(const float2*)(Rb + (long long)r1 * NHW + n);
                *(float2*)(Cb + (long long)r0 * NHW + n) =
                    make_float2(acc[mt][nt][0] + b0v + q0.x, acc[mt][nt][1] + b0v + q0.y);
                *(float2*)(Cb + (long long)r1 * NHW + n) =
                    make_float2(acc[mt][nt][2] + b1v + q1.x, acc[mt][nt][3] + b1v + q1.y);
            }
        }
    } else {
        __nv_bfloat16* ChB = Ch + (long long)bz * sCb;
        __nv_bfloat16* ClB = Cl + (long long)bz * sCb;
        #pragma unroll
        for (int mt = 0; mt < 4; mt++) {
            int r0 = m0 + wm + mt * 16 + (l >> 2);
            int r1 = r0 + 8;
            float b0v = 0.f, b1v = 0.f;
            if (EPI == 0) { b0v = bias[r0]; b1v = bias[r1]; }
            #pragma unroll
            for (int nt = 0; nt < 4; nt++) {
                int n = n0 + wn + nt * 8 + (l & 3) * 2;
                store_pair(ChB, ClB, (long long)r0 * NHW + n,
                           make_float2(acc[mt][nt][0] + b0v, acc[mt][nt][1] + b0v));
                store_pair(ChB, ClB, (long long)r1 * NHW + n,
                           make_float2(acc[mt][nt][2] + b1v, acc[mt][nt][3] + b1v));
            }
        }
    }
}

// ---------------- GroupNorm stats ----------------
__global__ __launch_bounds__(256) void gn_stats(const float* __restrict__ x,
                                                float* __restrict__ stats)
{
    __shared__ float sred[16];
    int b = blockIdx.x >> 5, g = blockIdx.x & 31;
    const float4* xp = reinterpret_cast<const float4*>(x + ((size_t)b * NC + g * 16) * NHW);
    const int N4 = 16 * NHW / 4;
    float s = 0.f, s2 = 0.f;
    for (int i = threadIdx.x; i < N4; i += 256) {
        float4 v = xp[i];
        s  += v.x + v.y + v.z + v.w;
        s2 += v.x * v.x + v.y * v.y + v.z * v.z + v.w * v.w;
    }
    #pragma unroll
    for (int o = 16; o > 0; o >>= 1) {
        s  += __shfl_xor_sync(0xffffffffu, s,  o);
        s2 += __shfl_xor_sync(0xffffffffu, s2, o);
    }
    int warp = threadIdx.x >> 5, lane = threadIdx.x & 31;
    if (lane == 0) { sred[warp] = s; sred[8 + warp] = s2; }
    __syncthreads();
    if (threadIdx.x == 0) {
        float ts = 0.f, ts2 = 0.f;
        #pragma unroll
        for (int wi = 0; wi < 8; wi++) { ts += sred[wi]; ts2 += sred[8 + wi]; }
        const float invn = 1.0f / (16 * NHW);
        float mean = ts * invn;
        float var  = ts2 * invn - mean * mean;
        stats[(b * 32 + g) * 2 + 0] = mean;
        stats[(b * 32 + g) * 2 + 1] = rsqrtf(var + 1e-5f);
    }
}

// ---------------- GroupNorm normalize + bf16 hi/lo split ----------------
__global__ __launch_bounds__(256) void gn_split(
    const float* __restrict__ x, const float* __restrict__ gamma,
    const float* __restrict__ beta, const float* __restrict__ stats,
    __nv_bfloat16* __restrict__ yh, __nv_bfloat16* __restrict__ yl)
{
    int b = blockIdx.y;
    long long i4 = (long long)blockIdx.x * 256 + threadIdx.x;
    int c = (int)((i4 * 4) >> 10);
    float mean = stats[(b * 32 + (c >> 4)) * 2 + 0];
    float rstd = stats[(b * 32 + (c >> 4)) * 2 + 1];
    float gm = gamma[c] * rstd;
    float gb = beta[c] - mean * gm;
    float4 v = reinterpret_cast<const float4*>(x + (size_t)b * CHW)[i4];
    v.x = v.x * gm + gb; v.y = v.y * gm + gb;
    v.z = v.z * gm + gb; v.w = v.w * gm + gb;
    __nv_bfloat162 h0 = __float22bfloat162_rn(make_float2(v.x, v.y));
    __nv_bfloat162 h1 = __float22bfloat162_rn(make_float2(v.z, v.w));
    float2 f0 = __bfloat1622float2(h0), f1 = __bfloat1622float2(h1);
    __nv_bfloat162 l0 = __float22bfloat162_rn(make_float2(v.x - f0.x, v.y - f0.y));
    __nv_bfloat162 l1 = __float22bfloat162_rn(make_float2(v.z - f1.x, v.w - f1.y));
    __nv_bfloat162* ph = reinterpret_cast<__nv_bfloat162*>(yh + (size_t)b * CHW);
    __nv_bfloat162* pl = reinterpret_cast<__nv_bfloat162*>(yl + (size_t)b * CHW);
    ph[i4 * 2] = h0; ph[i4 * 2 + 1] = h1;
    pl[i4 * 2] = l0; pl[i4 * 2 + 1] = l1;
}

// ---------------- weight hi/lo split ----------------
__global__ __launch_bounds__(256) void wsplit(const float* __restrict__ w,
                                              __nv_bfloat16* __restrict__ wh,
                                              __nv_bfloat16* __restrict__ wl, int n4)
{
    int i = blockIdx.x * 256 + threadIdx.x;
    if (i >= n4) return;
    float4 v = reinterpret_cast<const float4*>(w)[i];
    __nv_bfloat162 h0 = __float22bfloat162_rn(make_float2(v.x, v.y));
    __nv_bfloat162 h1 = __float22bfloat162_rn(make_float2(v.z, v.w));
    float2 f0 = __bfloat1622float2(h0), f1 = __bfloat1622float2(h1);
    __nv_bfloat162 l0 = __float22bfloat162_rn(make_float2(v.x - f0.x, v.y - f0.y));
    __nv_bfloat162 l1 = __float22bfloat162_rn(make_float2(v.z - f1.x, v.w - f1.y));
    reinterpret_cast<__nv_bfloat162*>(wh)[i * 2]     = h0;
    reinterpret_cast<__nv_bfloat162*>(wh)[i * 2 + 1] = h1;
    reinterpret_cast<__nv_bfloat162*>(wl)[i * 2]     = l0;
    reinterpret_cast<__nv_bfloat162*>(wl)[i * 2 + 1] = l1;
}

// ---------------- launch ----------------
extern "C" void kernel_launch(void* const* d_in, const int* in_sizes, int n_in,
                              void* d_out, int out_size)
{
    const float* x      = (const float*)d_in[0];
    const float* gamma  = (const float*)d_in[1];
    const float* beta   = (const float*)d_in[2];
    const float* qkv_w  = (const float*)d_in[3];
    const float* qkv_b  = (const float*)d_in[4];
    const float* proj_w = (const float*)d_in[5];
    const float* proj_b = (const float*)d_in[6];
    float* out = (float*)d_out;

    __nv_bfloat16 *qkvh, *qkvl, *hinh, *hinl, *Ph, *Pl, *Hh, *Hl, *wqh, *wql, *wph, *wpl;
    float* stats;
    cudaGetSymbolAddress((void**)&qkvh, g_qkvh);
    cudaGetSymbolAddress((void**)&qkvl, g_qkvl);
    cudaGetSymbolAddress((void**)&hinh, g_hinh);
    cudaGetSymbolAddress((void**)&hinl, g_hinl);
    cudaGetSymbolAddress((void**)&Ph,   g_Ph);
    cudaGetSymbolAddress((void**)&Pl,   g_Pl);
    cudaGetSymbolAddress((void**)&Hh,   g_Hh);
    cudaGetSymbolAddress((void**)&Hl,   g_Hl);
    cudaGetSymbolAddress((void**)&wqh,  g_wqh);
    cudaGetSymbolAddress((void**)&wql,  g_wql);
    cudaGetSymbolAddress((void**)&wph,  g_wph);
    cudaGetSymbolAddress((void**)&wpl,  g_wpl);
    cudaGetSymbolAddress((void**)&stats, g_stats);

    cudaFuncSetAttribute(tc_gemm<0, false, true >, cudaFuncAttributeMaxDynamicSharedMemorySize, SMEMB);
    cudaFuncSetAttribute(tc_gemm<1, true,  true >, cudaFuncAttributeMaxDynamicSharedMemorySize, SMEMB);
    cudaFuncSetAttribute(tc_gemm<2, false, false>, cudaFuncAttributeMaxDynamicSharedMemorySize, SMEMB);
    cudaFuncSetAttribute(tc_gemm<3, false, true >, cudaFuncAttributeMaxDynamicSharedMemorySize, SMEMB);

    const long long s3  = 3LL * CHW;
    const long long sSS = (long long)NHW * NHW;
    const float attn_scale = 1.0f / sqrtf((float)NC);

    // 1) operand prep
    gn_stats<<<NB * 32, 256>>>(x, stats);
    wsplit<<<(1536 * NC / 4 + 255) / 256, 256>>>(qkv_w, wqh, wql, 1536 * NC / 4);
    wsplit<<<(NC * NC / 4 + 255) / 256, 256>>>(proj_w, wph, wpl, NC * NC / 4);
    gn_split<<<dim3(CHW / 1024, NB), 256>>>(x, gamma, beta, stats, hinh, hinl);

    // 2) QKV = W @ gn(x): M=1536, N=1024, K=512.  A direct, B trans
    tc_gemm<0, false, true><<<dim3(8, 12, NB), 256, SMEMB>>>(
        wqh, wql, 0LL, NC, hinh, hinl, (long long)CHW, NHW, NC,
        nullptr, qkvh, qkvl, s3, qkv_b, nullptr, 1.0f);

    // 3) S = softmax32(alpha * Q^T K): M=N=1024, K=512. Both trans
    tc_gemm<1, true, true><<<dim3(8, 8, NB), 256, SMEMB>>>(
        qkvh, qkvl, s3, NHW, qkvh + CHW, qkvl + CHW, s3, NHW, NC,
        nullptr, Ph, Pl, sSS, nullptr, nullptr, attn_scale);

    // 4) H[c][p] = sum_q V[c][q] P[p][q]: M=512, N=1024, K=1024. Both direct
    tc_gemm<2, false, false><<<dim3(8, 4, NB), 256, SMEMB>>>(
        qkvh + 2LL * CHW, qkvl + 2LL * CHW, s3, NHW, Ph, Pl, sSS, NHW, NHW,
        nullptr, Hh, Hl, (long long)CHW, nullptr, nullptr, 1.0f);

    // 5) out = x + proj_w @ H + proj_b: M=512, N=1024, K=512. A direct, B trans
    tc_gemm<3, false, true><<<dim3(8, 4, NB), 256, SMEMB>>>(
        wph, wpl, 0LL, NC, Hh, Hl, (long long)CHW, NHW, NC,
        out, nullptr, nullptr, (long long)CHW, proj_b, x, 1.0f);
}

// round 8
// speedup vs baseline: 2.8242x; 1.0081x over previous
#include <cuda_runtime.h>
#include <cuda_bf16.h>
#include <math.h>
#include <stdint.h>

#define NB   32
#define NC   512
#define NHW  1024
#define CHW  (NC * NHW)

// ---------------- persistent scratch (hi/lo bf16 split operands) ----------------
__device__ __nv_bfloat16 g_qkvh[(size_t)NB * 3 * CHW];
__device__ __nv_bfloat16 g_qkvl[(size_t)NB * 3 * CHW];
__device__ __nv_bfloat16 g_hinh[(size_t)NB * CHW];
__device__ __nv_bfloat16 g_hinl[(size_t)NB * CHW];
__device__ __nv_bfloat16 g_Ph[(size_t)NB * NHW * NHW];
__device__ __nv_bfloat16 g_Pl[(size_t)NB * NHW * NHW];
__device__ __nv_bfloat16 g_Hh[(size_t)NB * CHW];
__device__ __nv_bfloat16 g_Hl[(size_t)NB * CHW];
__device__ __nv_bfloat16 g_wqh[1536 * NC], g_wql[1536 * NC];
__device__ __nv_bfloat16 g_wph[NC * NC],   g_wpl[NC * NC];

// ---------------- PTX helpers (baseline sm_80-era ISA only) ----------------
__device__ __forceinline__ uint32_t smem_u32(const void* p) {
    uint32_t a;
    asm("{ .reg .u64 t; cvta.to.shared.u64 t, %1; cvt.u32.u64 %0, t; }" : "=r"(a) : "l"(p));
    return a;
}
#define LDSM4(R, a) \
    asm volatile("ldmatrix.sync.aligned.m8n8.x4.shared.b16 {%0,%1,%2,%3}, [%4];" \
        : "=r"((R)[0]), "=r"((R)[1]), "=r"((R)[2]), "=r"((R)[3]) : "r"(a))
#define LDSM4T(R, a) \
    asm volatile("ldmatrix.sync.aligned.m8n8.x4.trans.shared.b16 {%0,%1,%2,%3}, [%4];" \
        : "=r"((R)[0]), "=r"((R)[1]), "=r"((R)[2]), "=r"((R)[3]) : "r"(a))
#define CP16(d, s) \
    asm volatile("cp.async.cg.shared.global [%0], [%1], 16;" :: "r"(d), "l"(s))
#define CP_COMMIT() asm volatile("cp.async.commit_group;" ::: "memory")
#define CP_WAIT1()  asm volatile("cp.async.wait_group 1;" ::: "memory")
#define CP_WAIT0()  asm volatile("cp.async.wait_group 0;" ::: "memory")

__device__ __forceinline__ void mma16816(float* d, const uint32_t* a, uint32_t b0, uint32_t b1) {
    asm volatile("mma.sync.aligned.m16n8k16.row.col.f32.bf16.bf16.f32 "
                 "{%0,%1,%2,%3}, {%4,%5,%6,%7}, {%8,%9}, {%0,%1,%2,%3};"
                 : "+f"(d[0]), "+f"(d[1]), "+f"(d[2]), "+f"(d[3])
                 : "r"(a[0]), "r"(a[1]), "r"(a[2]), "r"(a[3]), "r"(b0), "r"(b1));
}

__device__ __forceinline__ void store_pair(__nv_bfloat16* H, __nv_bfloat16* L,
                                           long long off, float2 v) {
    __nv_bfloat162 h = __float22bfloat162_rn(v);
    float2 hf = __bfloat1622float2(h);
    __nv_bfloat162 lo = __float22bfloat162_rn(make_float2(v.x - hf.x, v.y - hf.y));
    *reinterpret_cast<__nv_bfloat162*>(H + off) = h;
    *reinterpret_cast<__nv_bfloat162*>(L + off) = lo;
}

// smem: 3 stages x (AH | AL | BH | BL), swizzled tiles, no padding
//   direct tile: 128 rows x 64B,  chunk(16B) swizzle: c ^= (row>>1)&3
//   trans  tile:  32 rows x 256B, chunk(16B) swizzle: c ^= row&7
#define SLOT   8192
#define STAGEB 32768
#define SMEMB  98304

// 128 threads, 4 warps in 2x2 grid, warp tile 64x64, CTA tile 128x128.
// EPI: 0=QKV(+bias, bf16 out), 1=S(alpha + fused 32-wide softmax, bf16 out),
//      2=H(bf16 out), 3=proj(+bias+residual, fp32 out)
template<int EPI, bool TA, bool TB>
__global__ __launch_bounds__(128, 2)
void tc_gemm(const __nv_bfloat16* __restrict__ Ah_, const __nv_bfloat16* __restrict__ Al_,
             long long sAb, int lda,
             const __nv_bfloat16* __restrict__ Bh_, const __nv_bfloat16* __restrict__ Bl_,
             long long sBb, int ldb,
             int Ktot,
             float* __restrict__ Cf, __nv_bfloat16* __restrict__ Ch, __nv_bfloat16* __restrict__ Cl,
             long long sCb,
             const float* __restrict__ bias, const float* __restrict__ res, float alpha)
{
    extern __shared__ char sm[];
    const int tid = threadIdx.x, l = tid & 31, wid = tid >> 5;
    const int bz = blockIdx.z;
    const int m0 = blockIdx.y * 128, n0 = blockIdx.x * 128;
    const int wm = (wid >> 1) * 64, wn = (wid & 1) * 64;

    const __nv_bfloat16* Agh = Ah_ + bz * sAb + (TA ? (long long)m0 : (long long)m0 * lda);
    const __nv_bfloat16* Agl = Al_ + bz * sAb + (TA ? (long long)m0 : (long long)m0 * lda);
    const __nv_bfloat16* Bgh = Bh_ + bz * sBb + (TB ? (long long)n0 : (long long)n0 * ldb);
    const __nv_bfloat16* Bgl = Bl_ + bz * sBb + (TB ? (long long)n0 : (long long)n0 * ldb);

    const uint32_t smb = smem_u32(sm);

    // --- fragment lane bases (swizzled, same domains as R7) ---
    const uint32_t rdir = (uint32_t)(l & 15);
    const uint32_t dirLane = rdir * 64 + (((((rdir >> 1) & 3)) ^ (uint32_t)(l >> 4)) << 4);
    const uint32_t rr = (uint32_t)((l & 7) + ((l >> 4) << 3));
    const uint32_t g8 = (uint32_t)((l >> 3) & 1);
    const uint32_t trLane = rr * 256 + ((((uint32_t)(l & 7)) ^ g8) << 4);

    const uint32_t aLane = TA ? (trLane ^ (uint32_t)(wm * 2)) : (dirLane + wm * 64);
    const uint32_t bLane = TB ? (trLane ^ (uint32_t)(wn * 2)) : (dirLane + wn * 64);
    const uint32_t aH = TA ? 4096u : 0u;   // additive per-h (trans); direct uses XOR h<<5
    const uint32_t bH = TB ? 4096u : 0u;

    float acc[4][8][4];
    #pragma unroll
    for (int i = 0; i < 4; i++)
        #pragma unroll
        for (int j = 0; j < 8; j++)
            #pragma unroll
            for (int k = 0; k < 4; k++) acc[i][j][k] = 0.f;

    auto ISSUE = [&](int s, int buf) {
        uint32_t st = smb + buf * STAGEB;
        int k0 = s * 32;
        // ---- A ----
        if (TA) {
            #pragma unroll
            for (int i = 0; i < 4; i++) {
                int idx = tid + i * 128;
                uint32_t row = (uint32_t)idx >> 4, ch = (uint32_t)idx & 15;
                uint32_t d = st + row * 256 + ((ch ^ (row & 7)) << 4);
                CP16(d,        Agh + (long long)(k0 + (int)row) * lda + ch * 8);
                CP16(d + SLOT, Agl + (long long)(k0 + (int)row) * lda + ch * 8);
            }
        } else {
            #pragma unroll
            for (int i = 0; i < 4; i++) {
                int idx = tid + i * 128;
                uint32_t row = (uint32_t)idx >> 2, ch = (uint32_t)idx & 3;
                uint32_t d = st + row * 64 + ((ch ^ ((row >> 1) & 3)) << 4);
                CP16(d,        Agh + (long long)row * lda + k0 + ch * 8);
                CP16(d + SLOT, Agl + (long long)row * lda + k0 + ch * 8);
            }
        }
        // ---- B ----
        uint32_t sb2 = st + 2 * SLOT;
        if (TB) {
            #pragma unroll
            for (int i = 0; i < 4; i++) {
                int idx = tid + i * 128;
                uint32_t row = (uint32_t)idx >> 4, ch = (uint32_t)idx & 15;
                uint32_t d = sb2 + row * 256 + ((ch ^ (row & 7)) << 4);
                CP16(d,        Bgh + (long long)(k0 + (int)row) * ldb + ch * 8);
                CP16(d + SLOT, Bgl + (long long)(k0 + (int)row) * ldb + ch * 8);
            }
        } else {
            #pragma unroll
            for (int i = 0; i < 4; i++) {
                int idx = tid + i * 128;
                uint32_t row = (uint32_t)idx >> 2, ch = (uint32_t)idx & 3;
                uint32_t d = sb2 + row * 64 + ((ch ^ ((row >> 1) & 3)) << 4);
                CP16(d,        Bgh + (long long)row * ldb + k0 + ch * 8);
                CP16(d + SLOT, Bgl + (long long)row * ldb + k0 + ch * 8);
            }
        }
    };

    auto COMPUTE = [&](int buf) {
        uint32_t base = smb + buf * STAGEB;
        #pragma unroll
        for (int h = 0; h < 2; h++) {
            uint32_t BhF[4][4], BlF[4][4];
            #pragma unroll
            for (int g = 0; g < 4; g++) {
                uint32_t bd = base + 2 * SLOT;
                if (TB) { bd += bLane + h * bH; bd ^= (uint32_t)(g << 5); }
                else    { bd += bLane + g * 1024u; bd ^= (uint32_t)(h << 5); }
                if (TB) { LDSM4T(BhF[g], bd); LDSM4T(BlF[g], bd + SLOT); }
                else    { LDSM4 (BhF[g], bd); LDSM4 (BlF[g], bd + SLOT); }
            }
            #pragma unroll
            for (int mt = 0; mt < 4; mt++) {
                uint32_t AhF[4], AlF[4];
                uint32_t ad = base;
                if (TA) { ad += aLane + h * aH; ad ^= (uint32_t)(mt << 5); }
                else    { ad += aLane + mt * 1024u; ad ^= (uint32_t)(h << 5); }
                if (TA) { LDSM4T(AhF, ad); LDSM4T(AlF, ad + SLOT); }
                else    { LDSM4 (AhF, ad); LDSM4 (AlF, ad + SLOT); }
                // three nt-passes: same-acc MMAs are 8 apart -> no RAW stalls
                #pragma unroll
                for (int nt = 0; nt < 8; nt++)
                    mma16816(acc[mt][nt], AhF, BhF[nt >> 1][nt & 1], BhF[nt >> 1][2 + (nt & 1)]);
                #pragma unroll
                for (int nt = 0; nt < 8; nt++)
                    mma16816(acc[mt][nt], AhF, BlF[nt >> 1][nt & 1], BlF[nt >> 1][2 + (nt & 1)]);
                #pragma unroll
                for (int nt = 0; nt < 8; nt++)
                    mma16816(acc[mt][nt], AlF, BhF[nt >> 1][nt & 1], BhF[nt >> 1][2 + (nt & 1)]);
            }
        }
    };

    // ---- 3-stage cp.async pipeline ----
    const int NS = Ktot / 32;
    ISSUE(0, 0); CP_COMMIT();
    ISSUE(1, 1); CP_COMMIT();
    for (int s = 0; s < NS; s++) {
        if (s + 1 < NS) { CP_WAIT1(); } else { CP_WAIT0(); }
        __syncthreads();
        if (s + 2 < NS) {
            int b3 = s + 2; b3 = (b3 >= 3) ? (b3 % 3) : b3;
            ISSUE(s + 2, b3); CP_COMMIT();
        }
        COMPUTE(s % 3);
    }

    // ---- epilogue ----
    if (EPI == 1) {
        __nv_bfloat16* ChB = Ch + (long long)bz * sCb;
        __nv_bfloat16* ClB = Cl + (long long)bz * sCb;
        #pragma unroll
        for (int mt = 0; mt < 4; mt++) {
            int r0 = m0 + wm + mt * 16 + (l >> 2);
            int r1 = r0 + 8;
            #pragma unroll
            for (int seg = 0; seg < 2; seg++) {
                float vl[8], vh[8];
                #pragma unroll
                for (int j = 0; j < 4; j++) {
                    int nt = seg * 4 + j;
                    vl[2 * j]     = acc[mt][nt][0] * alpha;
                    vl[2 * j + 1] = acc[mt][nt][1] * alpha;
                    vh[2 * j]     = acc[mt][nt][2] * alpha;
                    vh[2 * j + 1] = acc[mt][nt][3] * alpha;
                }
                float m_lo = vl[0], m_hi = vh[0];
                #pragma unroll
                for (int j = 1; j < 8; j++) { m_lo = fmaxf(m_lo, vl[j]); m_hi = fmaxf(m_hi, vh[j]); }
                m_lo = fmaxf(m_lo, __shfl_xor_sync(0xffffffffu, m_lo, 1));
                m_lo = fmaxf(m_lo, __shfl_xor_sync(0xffffffffu, m_lo, 2));
                m_hi = fmaxf(m_hi, __shfl_xor_sync(0xffffffffu, m_hi, 1));
                m_hi = fmaxf(m_hi, __shfl_xor_sync(0xffffffffu, m_hi, 2));
                float s_lo = 0.f, s_hi = 0.f;
                #pragma unroll
                for (int j = 0; j < 8; j++) {
                    vl[j] = __expf(vl[j] - m_lo); s_lo += vl[j];
                    vh[j] = __expf(vh[j] - m_hi); s_hi += vh[j];
                }
                s_lo += __shfl_xor_sync(0xffffffffu, s_lo, 1);
                s_lo += __shfl_xor_sync(0xffffffffu, s_lo, 2);
                s_hi += __shfl_xor_sync(0xffffffffu, s_hi, 1);
                s_hi += __shfl_xor_sync(0xffffffffu, s_hi, 2);
                float i_lo = 1.0f / s_lo, i_hi = 1.0f / s_hi;
                #pragma unroll
                for (int j = 0; j < 4; j++) {
                    int n = n0 + wn + (seg * 4 + j) * 8 + (l & 3) * 2;
                    store_pair(ChB, ClB, (long long)r0 * NHW + n,
                               make_float2(vl[2 * j] * i_lo, vl[2 * j + 1] * i_lo));
                    store_pair(ChB, ClB, (long long)r1 * NHW + n,
                               make_float2(vh[2 * j] * i_hi, vh[2 * j + 1] * i_hi));
                }
            }
        }
    } else if (EPI == 3) {
        float* Cb = Cf + (long long)bz * sCb;
        const float* Rb = res + (long long)bz * sCb;
        #pragma unroll
        for (int mt = 0; mt < 4; mt++) {
            int r0 = m0 + wm + mt * 16 + (l >> 2);
            int r1 = r0 + 8;
            float b0v = bias[r0], b1v = bias[r1];
            #pragma unroll
            for (int nt = 0; nt < 8; nt++) {
                int n = n0 + wn + nt * 8 + (l & 3) * 2;
                float2 q0 = *(const float2*)(Rb + (long long)r0 * NHW + n);
                float2 q1 = *(const float2*)(Rb + (long long)r1 * NHW + n);
                *(float2*)(Cb + (long long)r0 * NHW + n) =
                    make_float2(acc[mt][nt][0] + b0v + q0.x, acc[mt][nt][1] + b0v + q0.y);
                *(float2*)(Cb + (long long)r1 * NHW + n) =
                    make_float2(acc[mt][nt][2] + b1v + q1.x, acc[mt][nt][3] + b1v + q1.y);
            }
        }
    } else {
        __nv_bfloat16* ChB = Ch + (long long)bz * sCb;
        __nv_bfloat16* ClB = Cl + (long long)bz * sCb;
        #pragma unroll
        for (int mt = 0; mt < 4; mt++) {
            int r0 = m0 + wm + mt * 16 + (l >> 2);
            int r1 = r0 + 8;
            float b0v = 0.f, b1v = 0.f;
            if (EPI == 0) { b0v = bias[r0]; b1v = bias[r1]; }
            #pragma unroll
            for (int nt = 0; nt < 8; nt++) {
                int n = n0 + wn + nt * 8 + (l & 3) * 2;
                store_pair(ChB, ClB, (long long)r0 * NHW + n,
                           make_float2(acc[mt][nt][0] + b0v, acc[mt][nt][1] + b0v));
                store_pair(ChB, ClB, (long long)r1 * NHW + n,
                           make_float2(acc[mt][nt][2] + b1v, acc[mt][nt][3] + b1v));
            }
        }
    }
}

// ---------------- fused GroupNorm: stats + normalize + bf16 hi/lo split ----------------
// One block per (b, g). Pass 1 computes mean/rstd; pass 2 re-reads (L1-hot) and writes.
__global__ __launch_bounds__(256) void gn_all(
    const float* __restrict__ x, const float* __restrict__ gamma,
    const float* __restrict__ beta,
    __nv_bfloat16* __restrict__ yh, __nv_bfloat16* __restrict__ yl)
{
    __shared__ float sred[16];
    int b = blockIdx.x >> 5, g = blockIdx.x & 31;
    const size_t gbase = (size_t)b * CHW + (size_t)g * 16 * NHW;
    const float4* xp = reinterpret_cast<const float4*>(x + gbase);
    const int N4 = 16 * NHW / 4;   // 4096
    float s = 0.f, s2 = 0.f;
    for (int i = threadIdx.x; i < N4; i += 256) {
        float4 v = xp[i];
        s  += v.x + v.y + v.z + v.w;
        s2 += v.x * v.x + v.y * v.y + v.z * v.z + v.w * v.w;
    }
    #pragma unroll
    for (int o = 16; o > 0; o >>= 1) {
        s  += __shfl_xor_sync(0xffffffffu, s,  o);
        s2 += __shfl_xor_sync(0xffffffffu, s2, o);
    }
    int warp = threadIdx.x >> 5, lane = threadIdx.x & 31;
    if (lane == 0) { sred[warp] = s; sred[8 + warp] = s2; }
    __syncthreads();
    if (threadIdx.x == 0) {
        float ts = 0.f, ts2 = 0.f;
        #pragma unroll
        for (int wi = 0; wi < 8; wi++) { ts += sred[wi]; ts2 += sred[8 + wi]; }
        const float invn = 1.0f / (16 * NHW);
        float mean = ts * invn;
        float var  = ts2 * invn - mean * mean;
        sred[0] = mean;
        sred[1] = rsqrtf(var + 1e-5f);
    }
    __syncthreads();
    float mean = sred[0], rstd = sred[1];

    __nv_bfloat162* ph = reinterpret_cast<__nv_bfloat162*>(yh + gbase);
    __nv_bfloat162* pl = reinterpret_cast<__nv_bfloat162*>(yl + gbase);
    for (int i = threadIdx.x; i < N4; i += 256) {
        int c = g * 16 + (i >> 8);             // 256 float4 per channel
        float gm = gamma[c] * rstd;
        float gb = beta[c] - mean * gm;
        float4 v = xp[i];
        v.x = v.x * gm + gb; v.y = v.y * gm + gb;
        v.z = v.z * gm + gb; v.w = v.w * gm + gb;
        __nv_bfloat162 h0 = __float22bfloat162_rn(make_float2(v.x, v.y));
        __nv_bfloat162 h1 = __float22bfloat162_rn(make_float2(v.z, v.w));
        float2 f0 = __bfloat1622float2(h0), f1 = __bfloat1622float2(h1);
        __nv_bfloat162 l0 = __float22bfloat162_rn(make_float2(v.x - f0.x, v.y - f0.y));
        __nv_bfloat162 l1 = __float22bfloat162_rn(make_float2(v.z - f1.x, v.w - f1.y));
        ph[i * 2] = h0; ph[i * 2 + 1] = h1;
        pl[i * 2] = l0; pl[i * 2 + 1] = l1;
    }
}

// ---------------- weight hi/lo split (both weights in one launch) ----------------
#define WQ4 (1536 * NC / 4)
#define WP4 (NC * NC / 4)
__global__ __launch_bounds__(256) void wsplit_all(
    const float* __restrict__ wq, const float* __restrict__ wp,
    __nv_bfloat16* __restrict__ wqh, __nv_bfloat16* __restrict__ wql,
    __nv_bfloat16* __restrict__ wph, __nv_bfloat16* __restrict__ wpl)
{
    int i = blockIdx.x * 256 + threadIdx.x;
    const float* w; __nv_bfloat16 *wh, *wl; int j;
    if (i < WQ4) { w = wq; wh = wqh; wl = wql; j = i; }
    else if (i < WQ4 + WP4) { w = wp; wh = wph; wl = wpl; j = i - WQ4; }
    else return;
    float4 v = reinterpret_cast<const float4*>(w)[j];
    __nv_bfloat162 h0 = __float22bfloat162_rn(make_float2(v.x, v.y));
    __nv_bfloat162 h1 = __float22bfloat162_rn(make_float2(v.z, v.w));
    float2 f0 = __bfloat1622float2(h0), f1 = __bfloat1622float2(h1);
    __nv_bfloat162 l0 = __float22bfloat162_rn(make_float2(v.x - f0.x, v.y - f0.y));
    __nv_bfloat162 l1 = __float22bfloat162_rn(make_float2(v.z - f1.x, v.w - f1.y));
    reinterpret_cast<__nv_bfloat162*>(wh)[j * 2]     = h0;
    reinterpret_cast<__nv_bfloat162*>(wh)[j * 2 + 1] = h1;
    reinterpret_cast<__nv_bfloat162*>(wl)[j * 2]     = l0;
    reinterpret_cast<__nv_bfloat162*>(wl)[j * 2 + 1] = l1;
}

// ---------------- launch ----------------
extern "C" void kernel_launch(void* const* d_in, const int* in_sizes, int n_in,
                              void* d_out, int out_size)
{
    const float* x      = (const float*)d_in[0];
    const float* gamma  = (const float*)d_in[1];
    const float* beta   = (const float*)d_in[2];
    const float* qkv_w  = (const float*)d_in[3];
    const float* qkv_b  = (const float*)d_in[4];
    const float* proj_w = (const float*)d_in[5];
    const float* proj_b = (const float*)d_in[6];
    float* out = (float*)d_out;

    __nv_bfloat16 *qkvh, *qkvl, *hinh, *hinl, *Ph, *Pl, *Hh, *Hl, *wqh, *wql, *wph, *wpl;
    cudaGetSymbolAddress((void**)&qkvh, g_qkvh);
    cudaGetSymbolAddress((void**)&qkvl, g_qkvl);
    cudaGetSymbolAddress((void**)&hinh, g_hinh);
    cudaGetSymbolAddress((void**)&hinl, g_hinl);
    cudaGetSymbolAddress((void**)&Ph,   g_Ph);
    cudaGetSymbolAddress((void**)&Pl,   g_Pl);
    cudaGetSymbolAddress((void**)&Hh,   g_Hh);
    cudaGetSymbolAddress((void**)&Hl,   g_Hl);
    cudaGetSymbolAddress((void**)&wqh,  g_wqh);
    cudaGetSymbolAddress((void**)&wql,  g_wql);
    cudaGetSymbolAddress((void**)&wph,  g_wph);
    cudaGetSymbolAddress((void**)&wpl,  g_wpl);

    cudaFuncSetAttribute(tc_gemm<0, false, true >, cudaFuncAttributeMaxDynamicSharedMemorySize, SMEMB);
    cudaFuncSetAttribute(tc_gemm<1, true,  true >, cudaFuncAttributeMaxDynamicSharedMemorySize, SMEMB);
    cudaFuncSetAttribute(tc_gemm<2, false, false>, cudaFuncAttributeMaxDynamicSharedMemorySize, SMEMB);
    cudaFuncSetAttribute(tc_gemm<3, false, true >, cudaFuncAttributeMaxDynamicSharedMemorySize, SMEMB);

    const long long s3  = 3LL * CHW;
    const long long sSS = (long long)NHW * NHW;
    const float attn_scale = 1.0f / sqrtf((float)NC);

    // 1) operand prep
    gn_all<<<NB * 32, 256>>>(x, gamma, beta, hinh, hinl);
    wsplit_all<<<(WQ4 + WP4 + 255) / 256, 256>>>(qkv_w, proj_w, wqh, wql, wph, wpl);

    // 2) QKV = W @ gn(x): M=1536, N=1024, K=512.  A direct, B trans
    tc_gemm<0, false, true><<<dim3(8, 12, NB), 128, SMEMB>>>(
        wqh, wql, 0LL, NC, hinh, hinl, (long long)CHW, NHW, NC,
        nullptr, qkvh, qkvl, s3, qkv_b, nullptr, 1.0f);

    // 3) S = softmax32(alpha * Q^T K): M=N=1024, K=512. Both trans
    tc_gemm<1, true, true><<<dim3(8, 8, NB), 128, SMEMB>>>(
        qkvh, qkvl, s3, NHW, qkvh + CHW, qkvl + CHW, s3, NHW, NC,
        nullptr, Ph, Pl, sSS, nullptr, nullptr, attn_scale);

    // 4) H[c][p] = sum_q V[c][q] P[p][q]: M=512, N=1024, K=1024. Both direct
    tc_gemm<2, false, false><<<dim3(8, 4, NB), 128, SMEMB>>>(
        qkvh + 2LL * CHW, qkvl + 2LL * CHW, s3, NHW, Ph, Pl, sSS, NHW, NHW,
        nullptr, Hh, Hl, (long long)CHW, nullptr, nullptr, 1.0f);

    // 5) out = x + proj_w @ H + proj_b: M=512, N=1024, K=512. A direct, B trans
    tc_gemm<3, false, true><<<dim3(8, 4, NB), 128, SMEMB>>>(
        wph, wpl, 0LL, NC, Hh, Hl, (long long)CHW, NHW, NC,
        out, nullptr, nullptr, (long long)CHW, proj_b, x, 1.0f);
}

// round 9
// speedup vs baseline: 6.3395x; 2.2447x over previous
#include <cuda_runtime.h>
#include <cuda_fp16.h>
#include <math.h>
#include <stdint.h>

#define NB   32
#define NC   512
#define NHW  1024
#define CHW  (NC * NHW)

// ---------------- persistent scratch (fp16 operands) ----------------
__device__ __half g_qkv[(size_t)NB * 3 * CHW];      // Q | K | V  [b][1536][1024]
__device__ __half g_hin[(size_t)NB * CHW];          // gn(x) [b][c][p]
__device__ __half g_P [(size_t)NB * NHW * NHW];     // post-softmax [b][p][q]
__device__ __half g_H [(size_t)NB * CHW];           // [b][c][p]
__device__ __half g_wq[1536 * NC];
__device__ __half g_wp[NC * NC];

// ---------------- PTX helpers (baseline sm_80-era ISA only) ----------------
__device__ __forceinline__ uint32_t smem_u32(const void* p) {
    uint32_t a;
    asm("{ .reg .u64 t; cvta.to.shared.u64 t, %1; cvt.u32.u64 %0, t; }" : "=r"(a) : "l"(p));
    return a;
}
#define LDSM4(R, a) \
    asm volatile("ldmatrix.sync.aligned.m8n8.x4.shared.b16 {%0,%1,%2,%3}, [%4];" \
        : "=r"((R)[0]), "=r"((R)[1]), "=r"((R)[2]), "=r"((R)[3]) : "r"(a))
#define LDSM4T(R, a) \
    asm volatile("ldmatrix.sync.aligned.m8n8.x4.trans.shared.b16 {%0,%1,%2,%3}, [%4];" \
        : "=r"((R)[0]), "=r"((R)[1]), "=r"((R)[2]), "=r"((R)[3]) : "r"(a))
#define CP16(d, s) \
    asm volatile("cp.async.cg.shared.global [%0], [%1], 16;" :: "r"(d), "l"(s))
#define CP_COMMIT() asm volatile("cp.async.commit_group;" ::: "memory")
#define CP_WAIT2()  asm volatile("cp.async.wait_group 2;" ::: "memory")
#define CP_WAIT1()  asm volatile("cp.async.wait_group 1;" ::: "memory")
#define CP_WAIT0()  asm volatile("cp.async.wait_group 0;" ::: "memory")

__device__ __forceinline__ void mma16816(float* d, const uint32_t* a, uint32_t b0, uint32_t b1) {
    asm volatile("mma.sync.aligned.m16n8k16.row.col.f32.f16.f16.f32 "
                 "{%0,%1,%2,%3}, {%4,%5,%6,%7}, {%8,%9}, {%0,%1,%2,%3};"
                 : "+f"(d[0]), "+f"(d[1]), "+f"(d[2]), "+f"(d[3])
                 : "r"(a[0]), "r"(a[1]), "r"(a[2]), "r"(a[3]), "r"(b0), "r"(b1));
}

__device__ __forceinline__ void store_h(__half* H, long long off, float2 v) {
    *reinterpret_cast<__half2*>(H + off) = __float22half2_rn(v);
}

// smem: 4 stages x (A | B), swizzled tiles, fp16 single
//   direct tile: 128 rows x 64B (32 k-values), chunk(16B) swizzle: c ^= (row>>1)&3
//   trans  tile:  32 rows x 256B (128 mn-values), chunk(16B) swizzle: c ^= row&7
#define SLOT   8192
#define STAGEB 16384
#define SMEMB  65536

// 128 threads, 4 warps in 2x2 grid, warp tile 64x64, CTA tile 128x128.
// EPI: 0=QKV(+bias), 1=S(alpha + fused 32-wide softmax), 2=H, 3=proj(+bias+residual, fp32)
template<int EPI, bool TA, bool TB>
__global__ __launch_bounds__(128, 2)
void tc_gemm(const __half* __restrict__ A_, long long sAb, int lda,
             const __half* __restrict__ B_, long long sBb, int ldb,
             int Ktot,
             float* __restrict__ Cf, __half* __restrict__ Ch, long long sCb,
             const float* __restrict__ bias, const float* __restrict__ res, float alpha)
{
    extern __shared__ char sm[];
    const int tid = threadIdx.x, l = tid & 31, wid = tid >> 5;
    const int bz = blockIdx.z;
    const int m0 = blockIdx.y * 128, n0 = blockIdx.x * 128;
    const int wm = (wid >> 1) * 64, wn = (wid & 1) * 64;

    const __half* Ag = A_ + bz * sAb + (TA ? (long long)m0 : (long long)m0 * lda);
    const __half* Bg = B_ + bz * sBb + (TB ? (long long)n0 : (long long)n0 * ldb);

    const uint32_t smb = smem_u32(sm);

    // --- fragment lane bases (swizzled, same domains as R7/R8) ---
    const uint32_t rdir = (uint32_t)(l & 15);
    const uint32_t dirLane = rdir * 64 + (((((rdir >> 1) & 3)) ^ (uint32_t)(l >> 4)) << 4);
    const uint32_t rr = (uint32_t)((l & 7) + ((l >> 4) << 3));
    const uint32_t g8 = (uint32_t)((l >> 3) & 1);
    const uint32_t trLane = rr * 256 + ((((uint32_t)(l & 7)) ^ g8) << 4);

    const uint32_t aLane = TA ? (trLane ^ (uint32_t)(wm * 2)) : (dirLane + wm * 64);
    const uint32_t bLane = TB ? (trLane ^ (uint32_t)(wn * 2)) : (dirLane + wn * 64);
    const uint32_t aH = TA ? 4096u : 0u;   // additive per-h (trans); direct uses XOR h<<5
    const uint32_t bH = TB ? 4096u : 0u;

    float acc[4][8][4];
    #pragma unroll
    for (int i = 0; i < 4; i++)
        #pragma unroll
        for (int j = 0; j < 8; j++)
            #pragma unroll
            for (int k = 0; k < 4; k++) acc[i][j][k] = 0.f;

    auto ISSUE = [&](int s, int buf) {
        uint32_t st = smb + buf * STAGEB;
        int k0 = s * 32;
        // ---- A ----
        if (TA) {
            #pragma unroll
            for (int i = 0; i < 4; i++) {
                int idx = tid + i * 128;
                uint32_t row = (uint32_t)idx >> 4, ch = (uint32_t)idx & 15;
                uint32_t d = st + row * 256 + ((ch ^ (row & 7)) << 4);
                CP16(d, Ag + (long long)(k0 + (int)row) * lda + ch * 8);
            }
        } else {
            #pragma unroll
            for (int i = 0; i < 4; i++) {
                int idx = tid + i * 128;
                uint32_t row = (uint32_t)idx >> 2, ch = (uint32_t)idx & 3;
                uint32_t d = st + row * 64 + ((ch ^ ((row >> 1) & 3)) << 4);
                CP16(d, Ag + (long long)row * lda + k0 + ch * 8);
            }
        }
        // ---- B ----
        uint32_t sb2 = st + SLOT;
        if (TB) {
            #pragma unroll
            for (int i = 0; i < 4; i++) {
                int idx = tid + i * 128;
                uint32_t row = (uint32_t)idx >> 4, ch = (uint32_t)idx & 15;
                uint32_t d = sb2 + row * 256 + ((ch ^ (row & 7)) << 4);
                CP16(d, Bg + (long long)(k0 + (int)row) * ldb + ch * 8);
            }
        } else {
            #pragma unroll
            for (int i = 0; i < 4; i++) {
                int idx = tid + i * 128;
                uint32_t row = (uint32_t)idx >> 2, ch = (uint32_t)idx & 3;
                uint32_t d = sb2 + row * 64 + ((ch ^ ((row >> 1) & 3)) << 4);
                CP16(d, Bg + (long long)row * ldb + k0 + ch * 8);
            }
        }
    };

    auto COMPUTE = [&](int buf) {
        uint32_t base = smb + buf * STAGEB;
        #pragma unroll
        for (int h = 0; h < 2; h++) {
            uint32_t BF[4][4];
            #pragma unroll
            for (int g = 0; g < 4; g++) {
                uint32_t bd = base + SLOT;
                if (TB) { bd += bLane + h * bH; bd ^= (uint32_t)(g << 5); }
                else    { bd += bLane + g * 1024u; bd ^= (uint32_t)(h << 5); }
                if (TB) { LDSM4T(BF[g], bd); }
                else    { LDSM4 (BF[g], bd); }
            }
            #pragma unroll
            for (int mt = 0; mt < 4; mt++) {
                uint32_t AF[4];
                uint32_t ad = base;
                if (TA) { ad += aLane + h * aH; ad ^= (uint32_t)(mt << 5); }
                else    { ad += aLane + mt * 1024u; ad ^= (uint32_t)(h << 5); }
                if (TA) { LDSM4T(AF, ad); }
                else    { LDSM4 (AF, ad); }
                #pragma unroll
                for (int nt = 0; nt < 8; nt++)
                    mma16816(acc[mt][nt], AF, BF[nt >> 1][nt & 1], BF[nt >> 1][2 + (nt & 1)]);
            }
        }
    };

    // ---- 4-stage cp.async pipeline ----
    const int NS = Ktot / 32;
    ISSUE(0, 0); CP_COMMIT();
    ISSUE(1, 1); CP_COMMIT();
    ISSUE(2, 2); CP_COMMIT();
    for (int s = 0; s < NS; s++) {
        int rem = NS - 1 - s;
        if (rem >= 2)      { CP_WAIT2(); }
        else if (rem == 1) { CP_WAIT1(); }
        else               { CP_WAIT0(); }
        __syncthreads();
        if (s + 3 < NS) { ISSUE(s + 3, (s + 3) & 3); CP_COMMIT(); }
        COMPUTE(s & 3);
    }

    // ---- epilogue ----
    if (EPI == 1) {
        __half* ChB = Ch + (long long)bz * sCb;
        #pragma unroll
        for (int mt = 0; mt < 4; mt++) {
            int r0 = m0 + wm + mt * 16 + (l >> 2);
            int r1 = r0 + 8;
            #pragma unroll
            for (int seg = 0; seg < 2; seg++) {
                float vl[8], vh[8];
                #pragma unroll
                for (int j = 0; j < 4; j++) {
                    int nt = seg * 4 + j;
                    vl[2 * j]     = acc[mt][nt][0] * alpha;
                    vl[2 * j + 1] = acc[mt][nt][1] * alpha;
                    vh[2 * j]     = acc[mt][nt][2] * alpha;
                    vh[2 * j + 1] = acc[mt][nt][3] * alpha;
                }
                float m_lo = vl[0], m_hi = vh[0];
                #pragma unroll
                for (int j = 1; j < 8; j++) { m_lo = fmaxf(m_lo, vl[j]); m_hi = fmaxf(m_hi, vh[j]); }
                m_lo = fmaxf(m_lo, __shfl_xor_sync(0xffffffffu, m_lo, 1));
                m_lo = fmaxf(m_lo, __shfl_xor_sync(0xffffffffu, m_lo, 2));
                m_hi = fmaxf(m_hi, __shfl_xor_sync(0xffffffffu, m_hi, 1));
                m_hi = fmaxf(m_hi, __shfl_xor_sync(0xffffffffu, m_hi, 2));
                float s_lo = 0.f, s_hi = 0.f;
                #pragma unroll
                for (int j = 0; j < 8; j++) {
                    vl[j] = __expf(vl[j] - m_lo); s_lo += vl[j];
                    vh[j] = __expf(vh[j] - m_hi); s_hi += vh[j];
                }
                s_lo += __shfl_xor_sync(0xffffffffu, s_lo, 1);
                s_lo += __shfl_xor_sync(0xffffffffu, s_lo, 2);
                s_hi += __shfl_xor_sync(0xffffffffu, s_hi, 1);
                s_hi += __shfl_xor_sync(0xffffffffu, s_hi, 2);
                float i_lo = 1.0f / s_lo, i_hi = 1.0f / s_hi;
                #pragma unroll
                for (int j = 0; j < 4; j++) {
                    int n = n0 + wn + (seg * 4 + j) * 8 + (l & 3) * 2;
                    store_h(ChB, (long long)r0 * NHW + n,
                            make_float2(vl[2 * j] * i_lo, vl[2 * j + 1] * i_lo));
                    store_h(ChB, (long long)r1 * NHW + n,
                            make_float2(vh[2 * j] * i_hi, vh[2 * j + 1] * i_hi));
                }
            }
        }
    } else if (EPI == 3) {
        float* Cb = Cf + (long long)bz * sCb;
        const float* Rb = res + (long long)bz * sCb;
        #pragma unroll
        for (int mt = 0; mt < 4; mt++) {
            int r0 = m0 + wm + mt * 16 + (l >> 2);
            int r1 = r0 + 8;
            float b0v = bias[r0], b1v = bias[r1];
            #pragma unroll
            for (int nt = 0; nt < 8; nt++) {
                int n = n0 + wn + nt * 8 + (l & 3) * 2;
                float2 q0 = *(const float2*)(Rb + (long long)r0 * NHW + n);
                float2 q1 = *(const float2*)(Rb + (long long)r1 * NHW + n);
                *(float2*)(Cb + (long long)r0 * NHW + n) =
                    make_float2(acc[mt][nt][0] + b0v + q0.x, acc[mt][nt][1] + b0v + q0.y);
                *(float2*)(Cb + (long long)r1 * NHW + n) =
                    make_float2(acc[mt][nt][2] + b1v + q1.x, acc[mt][nt][3] + b1v + q1.y);
            }
        }
    } else {
        __half* ChB = Ch + (long long)bz * sCb;
        #pragma unroll
        for (int mt = 0; mt < 4; mt++) {
            int r0 = m0 + wm + mt * 16 + (l >> 2);
            int r1 = r0 + 8;
            float b0v = 0.f, b1v = 0.f;
            if (EPI == 0) { b0v = bias[r0]; b1v = bias[r1]; }
            #pragma unroll
            for (int nt = 0; nt < 8; nt++) {
                int n = n0 + wn + nt * 8 + (l & 3) * 2;
                store_h(ChB, (long long)r0 * NHW + n,
                        make_float2(acc[mt][nt][0] + b0v, acc[mt][nt][1] + b0v));
                store_h(ChB, (long long)r1 * NHW + n,
                        make_float2(acc[mt][nt][2] + b1v, acc[mt][nt][3] + b1v));
            }
        }
    }
}

// ---------------- fused GroupNorm: stats + normalize + fp16 ----------------
__global__ __launch_bounds__(256) void gn_all(
    const float* __restrict__ x, const float* __restrict__ gamma,
    const float* __restrict__ beta, __half* __restrict__ y)
{
    __shared__ float sred[16];
    int b = blockIdx.x >> 5, g = blockIdx.x & 31;
    const size_t gbase = (size_t)b * CHW + (size_t)g * 16 * NHW;
    const float4* xp = reinterpret_cast<const float4*>(x + gbase);
    const int N4 = 16 * NHW / 4;   // 4096
    float s = 0.f, s2 = 0.f;
    for (int i = threadIdx.x; i < N4; i += 256) {
        float4 v = xp[i];
        s  += v.x + v.y + v.z + v.w;
        s2 += v.x * v.x + v.y * v.y + v.z * v.z + v.w * v.w;
    }
    #pragma unroll
    for (int o = 16; o > 0; o >>= 1) {
        s  += __shfl_xor_sync(0xffffffffu, s,  o);
        s2 += __shfl_xor_sync(0xffffffffu, s2, o);
    }
    int warp = threadIdx.x >> 5, lane = threadIdx.x & 31;
    if (lane == 0) { sred[warp] = s; sred[8 + warp] = s2; }
    __syncthreads();
    if (threadIdx.x == 0) {
        float ts = 0.f, ts2 = 0.f;
        #pragma unroll
        for (int wi = 0; wi < 8; wi++) { ts += sred[wi]; ts2 += sred[8 + wi]; }
        const float invn = 1.0f / (16 * NHW);
        float mean = ts * invn;
        float var  = ts2 * invn - mean * mean;
        sred[0] = mean;
        sred[1] = rsqrtf(var + 1e-5f);
    }
    __syncthreads();
    float mean = sred[0], rstd = sred[1];

    __half2* py = reinterpret_cast<__half2*>(y + gbase);
    for (int i = threadIdx.x; i < N4; i += 256) {
        int c = g * 16 + (i >> 8);
        float gm = gamma[c] * rstd;
        float gb = beta[c] - mean * gm;
        float4 v = xp[i];
        py[i * 2]     = __float22half2_rn(make_float2(v.x * gm + gb, v.y * gm + gb));
        py[i * 2 + 1] = __float22half2_rn(make_float2(v.z * gm + gb, v.w * gm + gb));
    }
}

// ---------------- weight fp16 convert (both weights, one launch) ----------------
#define WQ4 (1536 * NC / 4)
#define WP4 (NC * NC / 4)
__global__ __launch_bounds__(256) void wconv_all(
    const float* __restrict__ wq, const float* __restrict__ wp,
    __half* __restrict__ wqh, __half* __restrict__ wph)
{
    int i = blockIdx.x * 256 + threadIdx.x;
    const float* w; __half* wh; int j;
    if (i < WQ4) { w = wq; wh = wqh; j = i; }
    else if (i < WQ4 + WP4) { w = wp; wh = wph; j = i - WQ4; }
    else return;
    float4 v = reinterpret_cast<const float4*>(w)[j];
    reinterpret_cast<__half2*>(wh)[j * 2]     = __float22half2_rn(make_float2(v.x, v.y));
    reinterpret_cast<__half2*>(wh)[j * 2 + 1] = __float22half2_rn(make_float2(v.z, v.w));
}

// ---------------- launch ----------------
extern "C" void kernel_launch(void* const* d_in, const int* in_sizes, int n_in,
                              void* d_out, int out_size)
{
    const float* x      = (const float*)d_in[0];
    const float* gamma  = (const float*)d_in[1];
    const float* beta   = (const float*)d_in[2];
    const float* qkv_w  = (const float*)d_in[3];
    const float* qkv_b  = (const float*)d_in[4];
    const float* proj_w = (const float*)d_in[5];
    const float* proj_b = (const float*)d_in[6];
    float* out = (float*)d_out;

    __half *qkv, *hin, *P, *H, *wq, *wp;
    cudaGetSymbolAddress((void**)&qkv, g_qkv);
    cudaGetSymbolAddress((void**)&hin, g_hin);
    cudaGetSymbolAddress((void**)&P,   g_P);
    cudaGetSymbolAddress((void**)&H,   g_H);
    cudaGetSymbolAddress((void**)&wq,  g_wq);
    cudaGetSymbolAddress((void**)&wp,  g_wp);

    cudaFuncSetAttribute(tc_gemm<0, false, true >, cudaFuncAttributeMaxDynamicSharedMemorySize, SMEMB);
    cudaFuncSetAttribute(tc_gemm<1, true,  true >, cudaFuncAttributeMaxDynamicSharedMemorySize, SMEMB);
    cudaFuncSetAttribute(tc_gemm<2, false, false>, cudaFuncAttributeMaxDynamicSharedMemorySize, SMEMB);
    cudaFuncSetAttribute(tc_gemm<3, false, true >, cudaFuncAttributeMaxDynamicSharedMemorySize, SMEMB);

    const long long s3  = 3LL * CHW;
    const long long sSS = (long long)NHW * NHW;
    const float attn_scale = 1.0f / sqrtf((float)NC);

    // 1) operand prep
    gn_all<<<NB * 32, 256>>>(x, gamma, beta, hin);
    wconv_all<<<(WQ4 + WP4 + 255) / 256, 256>>>(qkv_w, proj_w, wq, wp);

    // 2) QKV = W @ gn(x): M=1536, N=1024, K=512.  A direct, B trans
    tc_gemm<0, false, true><<<dim3(8, 12, NB), 128, SMEMB>>>(
        wq, 0LL, NC, hin, (long long)CHW, NHW, NC,
        nullptr, qkv, s3, qkv_b, nullptr, 1.0f);

    // 3) S = softmax32(alpha * Q^T K): M=N=1024, K=512. Both trans
    tc_gemm<1, true, true><<<dim3(8, 8, NB), 128, SMEMB>>>(
        qkv, s3, NHW, qkv + CHW, s3, NHW, NC,
        nullptr, P, sSS, nullptr, nullptr, attn_scale);

    // 4) H[c][p] = sum_q V[c][q] P[p][q]: M=512, N=1024, K=1024. Both direct
    tc_gemm<2, false, false><<<dim3(8, 4, NB), 128, SMEMB>>>(
        qkv + 2LL * CHW, s3, NHW, P, sSS, NHW, NHW,
        nullptr, H, (long long)CHW, nullptr, nullptr, 1.0f);

    // 5) out = x + proj_w @ H + proj_b: M=512, N=1024, K=512. A direct, B trans
    tc_gemm<3, false, true><<<dim3(8, 4, NB), 128, SMEMB>>>(
        wp, 0LL, NC, H, (long long)CHW, NHW, NC,
        out, nullptr, (long long)CHW, proj_b, x, 1.0f);
}

// round 12
// speedup vs baseline: 7.0102x; 1.1058x over previous
#include <cuda_runtime.h>
#include <cuda_fp16.h>
#include <math.h>
#include <stdint.h>

#define NB   32
#define NC   512
#define NHW  1024
#define CHW  (NC * NHW)

// ---------------- persistent scratch (fp16 operands) ----------------
__device__ __half g_qkv[(size_t)NB * 3 * CHW];      // Q | K | V  [b][1536][1024]
__device__ __half g_hin[(size_t)NB * CHW];          // gn(x) [b][c][p]
__device__ __half g_P [(size_t)NB * NHW * NHW];     // post-softmax [b][p][q]
__device__ __half g_H [(size_t)NB * CHW];           // [b][c][p]
__device__ __half g_wq[1536 * NC];
__device__ __half g_wp[NC * NC];

// ---------------- PTX helpers (baseline sm_80-era ISA only) ----------------
__device__ __forceinline__ uint32_t smem_u32(const void* p) {
    uint32_t a;
    asm("{ .reg .u64 t; cvta.to.shared.u64 t, %1; cvt.u32.u64 %0, t; }" : "=r"(a) : "l"(p));
    return a;
}
#define LDSM4(R, a) \
    asm volatile("ldmatrix.sync.aligned.m8n8.x4.shared.b16 {%0,%1,%2,%3}, [%4];" \
        : "=r"((R)[0]), "=r"((R)[1]), "=r"((R)[2]), "=r"((R)[3]) : "r"(a))
#define LDSM4T(R, a) \
    asm volatile("ldmatrix.sync.aligned.m8n8.x4.trans.shared.b16 {%0,%1,%2,%3}, [%4];" \
        : "=r"((R)[0]), "=r"((R)[1]), "=r"((R)[2]), "=r"((R)[3]) : "r"(a))
#define CP16(d, s) \
    asm volatile("cp.async.cg.shared.global [%0], [%1], 16;" :: "r"(d), "l"(s))
#define CP_COMMIT() asm volatile("cp.async.commit_group;" ::: "memory")
#define CP_WAIT2()  asm volatile("cp.async.wait_group 2;" ::: "memory")
#define CP_WAIT1()  asm volatile("cp.async.wait_group 1;" ::: "memory")
#define CP_WAIT0()  asm volatile("cp.async.wait_group 0;" ::: "memory")

__device__ __forceinline__ void mma16816(float* d, const uint32_t* a, uint32_t b0, uint32_t b1) {
    asm volatile("mma.sync.aligned.m16n8k16.row.col.f32.f16.f16.f32 "
                 "{%0,%1,%2,%3}, {%4,%5,%6,%7}, {%8,%9}, {%0,%1,%2,%3};"
                 : "+f"(d[0]), "+f"(d[1]), "+f"(d[2]), "+f"(d[3])
                 : "r"(a[0]), "r"(a[1]), "r"(a[2]), "r"(a[3]), "r"(b0), "r"(b1));
}

__device__ __forceinline__ void store_h(__half* H, long long off, float2 v) {
    *reinterpret_cast<__half2*>(H + off) = __float22half2_rn(v);
}

// smem: 4 stages x (A | B), swizzled fp16 tiles
//   direct tile: 128 rows x 64B (32 k-values), chunk(16B) swizzle: c ^= (row>>1)&3
//   trans  tile:  32 rows x 256B (128 mn-values), chunk(16B) swizzle: c ^= row&7
#define SLOT   8192
#define STAGEB 16384
#define SMEMB  65536

// 128 threads, 4 warps in 2x2 grid, warp tile 64x64, CTA tile 128x128.
// EPI: 0=QKV(+bias), 1=S(alpha + fused 32-wide softmax), 2=H, 3=proj(+bias+residual, fp32)
template<int EPI, bool TA, bool TB>
__global__ __launch_bounds__(128, 2)
void tc_gemm(const __half* __restrict__ A_, long long sAb, int lda,
             const __half* __restrict__ B_, long long sBb, int ldb,
             int Ktot,
             float* __restrict__ Cf, __half* __restrict__ Ch, long long sCb,
             const float* __restrict__ bias, const float* __restrict__ res, float alpha)
{
    extern __shared__ char sm[];
    const int tid = threadIdx.x, l = tid & 31, wid = tid >> 5;
    const int bz = blockIdx.z;
    const int m0 = blockIdx.y * 128, n0 = blockIdx.x * 128;
    const int wm = (wid >> 1) * 64, wn = (wid & 1) * 64;

    const __half* Ag = A_ + bz * sAb + (TA ? (long long)m0 : (long long)m0 * lda);
    const __half* Bg = B_ + bz * sBb + (TB ? (long long)n0 : (long long)n0 * ldb);

    const uint32_t smb = smem_u32(sm);

    // ---- hoisted cp.async addressing (per-thread, constant per stage) ----
    // TA/TB (trans): row0 = tid>>4 (+8 per i), ch = tid&15; i-step smem 2048B
    // direct:        row0 = tid>>2 (+32 per i), ch = tid&3;  i-step smem 2048B
    uint32_t aSts0, bSts0;
    {
        if (TA) {
            uint32_t r0 = (uint32_t)tid >> 4, ch = (uint32_t)tid & 15;
            aSts0 = r0 * 256 + ((ch ^ (r0 & 7)) << 4);
        } else {
            uint32_t r0 = (uint32_t)tid >> 2, ch = (uint32_t)tid & 3;
            aSts0 = r0 * 64 + ((ch ^ ((r0 >> 1) & 3)) << 4);
        }
        if (TB) {
            uint32_t r0 = (uint32_t)tid >> 4, ch = (uint32_t)tid & 15;
            bSts0 = r0 * 256 + ((ch ^ (r0 & 7)) << 4);
        } else {
            uint32_t r0 = (uint32_t)tid >> 2, ch = (uint32_t)tid & 3;
            bSts0 = r0 * 64 + ((ch ^ ((r0 >> 1) & 3)) << 4);
        }
    }
    const long long aGI  = TA ? 8LL * lda : 32LL * lda;   // per-i global step
    const long long bGI  = TB ? 8LL * ldb : 32LL * ldb;
    const long long aAdv = TA ? 32LL * lda : 32LL;        // per-stage advance
    const long long bAdv = TB ? 32LL * ldb : 32LL;
    const __half* Ap = Ag + (TA ? ((long long)((uint32_t)tid >> 4)) * lda + ((tid & 15) * 8)
                                : ((long long)((uint32_t)tid >> 2)) * lda + ((tid & 3) * 8));
    const __half* Bp = Bg + (TB ? ((long long)((uint32_t)tid >> 4)) * ldb + ((tid & 15) * 8)
                                : ((long long)((uint32_t)tid >> 2)) * ldb + ((tid & 3) * 8));

    // ---- hoisted ldmatrix fragment addresses (16 regs) ----
    const uint32_t rdir = (uint32_t)(l & 15);
    const uint32_t dirLane = rdir * 64 + (((((rdir >> 1) & 3)) ^ (uint32_t)(l >> 4)) << 4);
    const uint32_t rr = (uint32_t)((l & 7) + ((l >> 4) << 3));
    const uint32_t g8 = (uint32_t)((l >> 3) & 1);
    const uint32_t trLane = rr * 256 + ((((uint32_t)(l & 7)) ^ g8) << 4);
    const uint32_t aLane = TA ? (trLane ^ (uint32_t)(wm * 2)) : (dirLane + wm * 64);
    const uint32_t bLane = TB ? (trLane ^ (uint32_t)(wn * 2)) : (dirLane + wn * 64);

    uint32_t adA[2][4], adB[2][4];
    #pragma unroll
    for (int h = 0; h < 2; h++) {
        #pragma unroll
        for (int g = 0; g < 4; g++) {
            uint32_t a0;
            if (TA) { a0 = aLane + h * 4096u; a0 ^= (uint32_t)(g << 5); }
            else    { a0 = aLane + g * 1024u; a0 ^= (uint32_t)(h << 5); }
            adA[h][g] = smb + a0;
            uint32_t b0;
            if (TB) { b0 = bLane + h * 4096u; b0 ^= (uint32_t)(g << 5); }
            else    { b0 = bLane + g * 1024u; b0 ^= (uint32_t)(h << 5); }
            adB[h][g] = smb + SLOT + b0;
        }
    }

    float acc[4][8][4];
    #pragma unroll
    for (int i = 0; i < 4; i++)
        #pragma unroll
        for (int j = 0; j < 8; j++)
            #pragma unroll
            for (int k = 0; k < 4; k++) acc[i][j][k] = 0.f;

    auto ISSUE = [&](uint32_t buf) {
        uint32_t st = smb + buf * STAGEB;
        #pragma unroll
        for (int i = 0; i < 4; i++)
            CP16(st + aSts0 + i * 2048, Ap + i * aGI);
        #pragma unroll
        for (int i = 0; i < 4; i++)
            CP16(st + SLOT + bSts0 + i * 2048, Bp + i * bGI);
        Ap += aAdv; Bp += bAdv;
    };

    auto COMPUTE = [&](uint32_t buf) {
        const uint32_t bo = buf * STAGEB;
        #pragma unroll
        for (int h = 0; h < 2; h++) {
            uint32_t BF[4][4];
            #pragma unroll
            for (int g = 0; g < 4; g++) {
                if (TB) { LDSM4T(BF[g], adB[h][g] + bo); }
                else    { LDSM4 (BF[g], adB[h][g] + bo); }
            }
            #pragma unroll
            for (int mt = 0; mt < 4; mt++) {
                uint32_t AF[4];
                if (TA) { LDSM4T(AF, adA[h][mt] + bo); }
                else    { LDSM4 (AF, adA[h][mt] + bo); }
                #pragma unroll
                for (int nt = 0; nt < 8; nt++)
                    mma16816(acc[mt][nt], AF, BF[nt >> 1][nt & 1], BF[nt >> 1][2 + (nt & 1)]);
            }
        }
    };

    // ---- 4-stage cp.async pipeline, unrolled x4 (NS is 16 or 32) ----
    const int NS = Ktot / 32;
    ISSUE(0); CP_COMMIT();
    ISSUE(1); CP_COMMIT();
    ISSUE(2); CP_COMMIT();
    for (int s = 0; s < NS; s += 4) {
        #pragma unroll
        for (int j = 0; j < 4; j++) {
            int ss = s + j;
            int rem = NS - 1 - ss;
            if (rem >= 2)      { CP_WAIT2(); }
            else if (rem == 1) { CP_WAIT1(); }
            else               { CP_WAIT0(); }
            __syncthreads();
            if (ss + 3 < NS) { ISSUE((uint32_t)((j + 3) & 3)); CP_COMMIT(); }
            COMPUTE((uint32_t)j);
        }
    }

    // ---- epilogue ----
    if (EPI == 1) {
        __half* ChB = Ch + (long long)bz * sCb;
        #pragma unroll
        for (int mt = 0; mt < 4; mt++) {
            int r0 = m0 + wm + mt * 16 + (l >> 2);
            int r1 = r0 + 8;
            #pragma unroll
            for (int seg = 0; seg < 2; seg++) {
                float vl[8], vh[8];
                #pragma unroll
                for (int j = 0; j < 4; j++) {
                    int nt = seg * 4 + j;
                    vl[2 * j]     = acc[mt][nt][0] * alpha;
                    vl[2 * j + 1] = acc[mt][nt][1] * alpha;
                    vh[2 * j]     = acc[mt][nt][2] * alpha;
                    vh[2 * j + 1] = acc[mt][nt][3] * alpha;
                }
                float m_lo = vl[0], m_hi = vh[0];
                #pragma unroll
                for (int j = 1; j < 8; j++) { m_lo = fmaxf(m_lo, vl[j]); m_hi = fmaxf(m_hi, vh[j]); }
                m_lo = fmaxf(m_lo, __shfl_xor_sync(0xffffffffu, m_lo, 1));
                m_lo = fmaxf(m_lo, __shfl_xor_sync(0xffffffffu, m_lo, 2));
                m_hi = fmaxf(m_hi, __shfl_xor_sync(0xffffffffu, m_hi, 1));
                m_hi = fmaxf(m_hi, __shfl_xor_sync(0xffffffffu, m_hi, 2));
                float s_lo = 0.f, s_hi = 0.f;
                #pragma unroll
                for (int j = 0; j < 8; j++) {
                    vl[j] = __expf(vl[j] - m_lo); s_lo += vl[j];
                    vh[j] = __expf(vh[j] - m_hi); s_hi += vh[j];
                }
                s_lo += __shfl_xor_sync(0xffffffffu, s_lo, 1);
                s_lo += __shfl_xor_sync(0xffffffffu, s_lo, 2);
                s_hi += __shfl_xor_sync(0xffffffffu, s_hi, 1);
                s_hi += __shfl_xor_sync(0xffffffffu, s_hi, 2);
                float i_lo = 1.0f / s_lo, i_hi = 1.0f / s_hi;
                #pragma unroll
                for (int j = 0; j < 4; j++) {
                    int n = n0 + wn + (seg * 4 + j) * 8 + (l & 3) * 2;
                    store_h(ChB, (long long)r0 * NHW + n,
                            make_float2(vl[2 * j] * i_lo, vl[2 * j + 1] * i_lo));
                    store_h(ChB, (long long)r1 * NHW + n,
                            make_float2(vh[2 * j] * i_hi, vh[2 * j + 1] * i_hi));
                }
            }
        }
    } else if (EPI == 3) {
        float* Cb = Cf + (long long)bz * sCb;
        const float* Rb = res + (long long)bz * sCb;
        #pragma unroll
        for (int mt = 0; mt < 4; mt++) {
            int r0 = m0 + wm + mt * 16 + (l >> 2);
            int r1 = r0 + 8;
            float b0v = bias[r0], b1v = bias[r1];
            #pragma unroll
            for (int nt = 0; nt < 8; nt++) {
                int n = n0 + wn + nt * 8 + (l & 3) * 2;
                float2 q0 = *(const float2*)(Rb + (long long)r0 * NHW + n);
                float2 q1 = *(const float2*)(Rb + (long long)r1 * NHW + n);
                *(float2*)(Cb + (long long)r0 * NHW + n) =
                    make_float2(acc[mt][nt][0] + b0v + q0.x, acc[mt][nt][1] + b0v + q0.y);
                *(float2*)(Cb + (long long)r1 * NHW + n) =
                    make_float2(acc[mt][nt][2] + b1v + q1.x, acc[mt][nt][3] + b1v + q1.y);
            }
        }
    } else {
        __half* ChB = Ch + (long long)bz * sCb;
        #pragma unroll
        for (int mt = 0; mt < 4; mt++) {
            int r0 = m0 + wm + mt * 16 + (l >> 2);
            int r1 = r0 + 8;
            float b0v = 0.f, b1v = 0.f;
            if (EPI == 0) { b0v = bias[r0]; b1v = bias[r1]; }
            #pragma unroll
            for (int nt = 0; nt < 8; nt++) {
                int n = n0 + wn + nt * 8 + (l & 3) * 2;
                store_h(ChB, (long long)r0 * NHW + n,
                        make_float2(acc[mt][nt][0] + b0v, acc[mt][nt][1] + b0v));
                store_h(ChB, (long long)r1 * NHW + n,
                        make_float2(acc[mt][nt][2] + b1v, acc[mt][nt][3] + b1v));
            }
        }
    }
}

// ---------------- fused GroupNorm: stats + normalize + fp16 ----------------
__global__ __launch_bounds__(256) void gn_all(
    const float* __restrict__ x, const float* __restrict__ gamma,
    const float* __restrict__ beta, __half* __restrict__ y)
{
    __shared__ float sred[16];
    int b = blockIdx.x >> 5, g = blockIdx.x & 31;
    const size_t gbase = (size_t)b * CHW + (size_t)g * 16 * NHW;
    const float4* xp = reinterpret_cast<const float4*>(x + gbase);
    const int N4 = 16 * NHW / 4;   // 4096
    float s = 0.f, s2 = 0.f;
    for (int i = threadIdx.x; i < N4; i += 256) {
        float4 v = xp[i];
        s  += v.x + v.y + v.z + v.w;
        s2 += v.x * v.x + v.y * v.y + v.z * v.z + v.w * v.w;
    }
    #pragma unroll
    for (int o = 16; o > 0; o >>= 1) {
        s  += __shfl_xor_sync(0xffffffffu, s,  o);
        s2 += __shfl_xor_sync(0xffffffffu, s2, o);
    }
    int warp = threadIdx.x >> 5, lane = threadIdx.x & 31;
    if (lane == 0) { sred[warp] = s; sred[8 + warp] = s2; }
    __syncthreads();
    if (threadIdx.x == 0) {
        float ts = 0.f, ts2 = 0.f;
        #pragma unroll
        for (int wi = 0; wi < 8; wi++) { ts += sred[wi]; ts2 += sred[8 + wi]; }
        const float invn = 1.0f / (16 * NHW);
        float mean = ts * invn;
        float var  = ts2 * invn - mean * mean;
        sred[0] = mean;
        sred[1] = rsqrtf(var + 1e-5f);
    }
    __syncthreads();
    float mean = sred[0], rstd = sred[1];

    __half2* py = reinterpret_cast<__half2*>(y + gbase);
    for (int i = threadIdx.x; i < N4; i += 256) {
        int c = g * 16 + (i >> 8);
        float gm = gamma[c] * rstd;
        float gb = beta[c] - mean * gm;
        float4 v = xp[i];
        py[i * 2]     = __float22half2_rn(make_float2(v.x * gm + gb, v.y * gm + gb));
        py[i * 2 + 1] = __float22half2_rn(make_float2(v.z * gm + gb, v.w * gm + gb));
    }
}

// ---------------- weight fp16 convert (both weights, one launch) ----------------
#define WQ4 (1536 * NC / 4)
#define WP4 (NC * NC / 4)
__global__ __launch_bounds__(256) void wconv_all(
    const float* __restrict__ wq, const float* __restrict__ wp,
    __half* __restrict__ wqh, __half* __restrict__ wph)
{
    int i = blockIdx.x * 256 + threadIdx.x;
    const float* w; __half* wh; int j;
    if (i < WQ4) { w = wq; wh = wqh; j = i; }
    else if (i < WQ4 + WP4) { w = wp; wh = wph; j = i - WQ4; }
    else return;
    float4 v = reinterpret_cast<const float4*>(w)[j];
    reinterpret_cast<__half2*>(wh)[j * 2]     = __float22half2_rn(make_float2(v.x, v.y));
    reinterpret_cast<__half2*>(wh)[j * 2 + 1] = __float22half2_rn(make_float2(v.z, v.w));
}

// ---------------- launch ----------------
extern "C" void kernel_launch(void* const* d_in, const int* in_sizes, int n_in,
                              void* d_out, int out_size)
{
    const float* x      = (const float*)d_in[0];
    const float* gamma  = (const float*)d_in[1];
    const float* beta   = (const float*)d_in[2];
    const float* qkv_w  = (const float*)d_in[3];
    const float* qkv_b  = (const float*)d_in[4];
    const float* proj_w = (const float*)d_in[5];
    const float* proj_b = (const float*)d_in[6];
    float* out = (float*)d_out;

    __half *qkv, *hin, *P, *H, *wq, *wp;
    cudaGetSymbolAddress((void**)&qkv, g_qkv);
    cudaGetSymbolAddress((void**)&hin, g_hin);
    cudaGetSymbolAddress((void**)&P,   g_P);
    cudaGetSymbolAddress((void**)&H,   g_H);
    cudaGetSymbolAddress((void**)&wq,  g_wq);
    cudaGetSymbolAddress((void**)&wp,  g_wp);

    cudaFuncSetAttribute(tc_gemm<0, false, true >, cudaFuncAttributeMaxDynamicSharedMemorySize, SMEMB);
    cudaFuncSetAttribute(tc_gemm<1, true,  true >, cudaFuncAttributeMaxDynamicSharedMemorySize, SMEMB);
    cudaFuncSetAttribute(tc_gemm<2, false, false>, cudaFuncAttributeMaxDynamicSharedMemorySize, SMEMB);
    cudaFuncSetAttribute(tc_gemm<3, false, true >, cudaFuncAttributeMaxDynamicSharedMemorySize, SMEMB);

    const long long s3  = 3LL * CHW;
    const long long sSS = (long long)NHW * NHW;
    const float attn_scale = 1.0f / sqrtf((float)NC);

    // 1) operand prep
    gn_all<<<NB * 32, 256>>>(x, gamma, beta, hin);
    wconv_all<<<(WQ4 + WP4 + 255) / 256, 256>>>(qkv_w, proj_w, wq, wp);

    // 2) QKV = W @ gn(x): M=1536, N=1024, K=512.  A direct, B trans
    tc_gemm<0, false, true><<<dim3(8, 12, NB), 128, SMEMB>>>(
        wq, 0LL, NC, hin, (long long)CHW, NHW, NC,
        nullptr, qkv, s3, qkv_b, nullptr, 1.0f);

    // 3) S = softmax32(alpha * Q^T K): M=N=1024, K=512. Both trans
    tc_gemm<1, true, true><<<dim3(8, 8, NB), 128, SMEMB>>>(
        qkv, s3, NHW, qkv + CHW, s3, NHW, NC,
        nullptr, P, sSS, nullptr, nullptr, attn_scale);

    // 4) H[c][p] = sum_q V[c][q] P[p][q]: M=512, N=1024, K=1024. Both direct
    tc_gemm<2, false, false><<<dim3(8, 4, NB), 128, SMEMB>>>(
        qkv + 2LL * CHW, s3, NHW, P, sSS, NHW, NHW,
        nullptr, H, (long long)CHW, nullptr, nullptr, 1.0f);

    // 5) out = x + proj_w @ H + proj_b: M=512, N=1024, K=512. A direct, B trans
    tc_gemm<3, false, true><<<dim3(8, 4, NB), 128, SMEMB>>>(
        wp, 0LL, NC, H, (long long)CHW, NHW, NC,
        out, nullptr, (long long)CHW, proj_b, x, 1.0f);
}